// round 5
// baseline (speedup 1.0000x reference)
#include <cuda_runtime.h>
#include <cstdint>
#include <math.h>
#include <stddef.h>

// ---------------- scratch (device globals; no allocations allowed) ----------
__device__ float g_h  [1024 * 256];
__device__ float g_hi [1024 * 256];
__device__ float g_hj [1024 * 256];
__device__ float g_agg[1024 * 256];
__device__ float g_n1 [1024 * 256];
__device__ float g_n2 [1024 * 256];
__device__ float g_enc[1024 * 256];
__device__ float g_k  [1024 * 256];
__device__ float g_v  [1024 * 256];
__device__ float g_q  [64 * 256];
__device__ float g_oA [64 * 256];
__device__ float g_m1 [64 * 256];
__device__ float g_m2 [64 * 256];
__device__ float g_w2t[256 * 256];   // W2 transposed, tf32-rounded: w2t[n][k] = rnd(W2[k][n])

// ---------------- helpers ----------------------------------------------------
__device__ __forceinline__ uint32_t f2tf32(float f) {
    uint32_t r;
    asm("cvt.rna.tf32.f32 %0, %1;" : "=r"(r) : "f"(f));
    return r;
}
// m16n8k8 tf32 MMA (baseline PTX, sm_80+): D = A@B + D, row.col
__device__ __forceinline__ void mma_tf32(float* c, const uint32_t* a, const uint32_t* bf) {
    asm volatile(
        "mma.sync.aligned.m16n8k8.row.col.f32.tf32.tf32.f32 "
        "{%0,%1,%2,%3}, {%4,%5,%6,%7}, {%8,%9}, {%0,%1,%2,%3};"
        : "+f"(c[0]), "+f"(c[1]), "+f"(c[2]), "+f"(c[3])
        : "r"(a[0]), "r"(a[1]), "r"(a[2]), "r"(a[3]), "r"(bf[0]), "r"(bf[1]));
}

// ---------------- prep: W2 (256x256, row-major [k][n]) -> w2t[n][k], tf32 ----
__global__ void prep_w2t(const float* __restrict__ W2, float* __restrict__ w2t) {
    int n = blockIdx.x, k = threadIdx.x;
    w2t[n * 256 + k] = __uint_as_float(f2tf32(W2[k * 256 + n]));
}

// ---------------- merged, double-buffered edge-MLP + adjacency contraction ---
// Per block (i, b): 8 steps s = (jh 0..1) x (kc 0..3):
//   A[128j x 64k] = tf32(relu(hi[b,i,:] + hj[b, jh*128+j, :]))  (buf s&1)
//   W[256n x 64k] = w2t slice                                   (buf s&1)
//   C[256h] accumulated via m16n8k8; after each jh: bias+relu+adj-reduce
// 256 threads = 8 warps: jm = w&1 (64j), hn = w>>1 (64h). C[4][8][4]=128 regs.
static constexpr int ES = 68;   // 64 + 4 pad -> conflict-free fragment LDS
// SMEM floats: ci@0[256] adjs@256[256] b2s@512[256] part@768[512]
//              A bufs @1280 (2 x 128*68)   W bufs @18688 (2 x 256*68)
static constexpr int E_A0 = 1280;
static constexpr int E_A1 = 1280 + 128 * ES;          // 9984
static constexpr int E_W0 = E_A1 + 128 * ES;          // 18688
static constexpr int E_W1 = E_W0 + 256 * ES;          // 36096
static constexpr int EDGE_SMEM_BYTES = (E_W1 + 256 * ES) * 4;   // 214016

__global__ void __launch_bounds__(256, 1)
edge_mma2(const float* __restrict__ hi, const float* __restrict__ hjp,
          const float* __restrict__ w2t, const float* __restrict__ b2,
          const float* __restrict__ adj, float* __restrict__ agg)
{
    extern __shared__ float sm[];
    float* ci   = sm;
    float* adjs = sm + 256;
    float* b2s  = sm + 512;
    float* part = sm + 768;

    const int tid = threadIdx.x, lane = tid & 31, w = tid >> 5;
    const int i = blockIdx.x, b = blockIdx.y;
    const size_t row = (size_t)(b * 256 + i) * 256;

    ci[tid]   = hi[row + tid];
    adjs[tid] = adj[row + tid];
    b2s[tid]  = b2[tid];
    __syncthreads();

    const int g  = lane >> 2;       // 0..7
    const int tg = lane & 3;        // 0..3
    const int jm = w & 1;           // j half (64) within step's 128 rows
    const int hn = w >> 1;          // h tile (64 wide)

    const float* hjb = hjp + (size_t)b * 65536;
    const int kq = tid & 15;        // float4 within 64-k chunk
    const int jr = tid >> 4;        // 0..15 row base per fill pass

    float C[4][8][4];
    #pragma unroll
    for (int mt = 0; mt < 4; ++mt)
        #pragma unroll
        for (int nt = 0; nt < 8; ++nt)
            #pragma unroll
            for (int r = 0; r < 4; ++r) C[mt][nt][r] = 0.f;
    float acc = 0.f;

    auto fill = [&](int s, int bf) {
        const int jh = s >> 2, kc = s & 3;
        const float4 cv = *(const float4*)(ci + kc * 64 + kq * 4);
        float* Ab = sm + (bf ? E_A1 : E_A0);
        float* Wb = sm + (bf ? E_W1 : E_W0);
        #pragma unroll
        for (int p = 0; p < 8; ++p) {
            const int r = p * 16 + jr;
            float4 hv = *(const float4*)(hjb + (size_t)(jh * 128 + r) * 256 + kc * 64 + kq * 4);
            uint4 o;
            o.x = f2tf32(fmaxf(cv.x + hv.x, 0.f));
            o.y = f2tf32(fmaxf(cv.y + hv.y, 0.f));
            o.z = f2tf32(fmaxf(cv.z + hv.z, 0.f));
            o.w = f2tf32(fmaxf(cv.w + hv.w, 0.f));
            *(uint4*)(Ab + r * ES + kq * 4) = o;
        }
        #pragma unroll
        for (int p = 0; p < 16; ++p) {
            const int r = p * 16 + jr;
            float4 wv = *(const float4*)(w2t + (size_t)r * 256 + kc * 64 + kq * 4);
            *(float4*)(Wb + r * ES + kq * 4) = wv;
        }
    };

    fill(0, 0);
    __syncthreads();

    for (int s = 0; s < 8; ++s) {
        const int bf = s & 1;
        if (s < 7) fill(s + 1, bf ^ 1);

        const uint32_t* ap = (const uint32_t*)(sm + (bf ? E_A1 : E_A0));
        const uint32_t* wp = (const uint32_t*)(sm + (bf ? E_W1 : E_W0));
        #pragma unroll
        for (int ks = 0; ks < 8; ++ks) {
            uint32_t afr[4][4];
            #pragma unroll
            for (int mt = 0; mt < 4; ++mt) {
                int r0 = (jm * 64 + mt * 16 + g) * ES + ks * 8;
                afr[mt][0] = ap[r0 + tg];
                afr[mt][1] = ap[r0 + 8 * ES + tg];
                afr[mt][2] = ap[r0 + tg + 4];
                afr[mt][3] = ap[r0 + 8 * ES + tg + 4];
            }
            #pragma unroll
            for (int nt = 0; nt < 8; ++nt) {
                int r0 = (hn * 64 + nt * 8 + g) * ES + ks * 8;
                uint32_t bfr[2];
                bfr[0] = wp[r0 + tg];
                bfr[1] = wp[r0 + tg + 4];
                #pragma unroll
                for (int mt = 0; mt < 4; ++mt)
                    mma_tf32(C[mt][nt], afr[mt], bfr);
            }
        }

        if ((s & 3) == 3) {          // end of a jh pass: fused epilogue
            const int jh = s >> 2;
            float ps[8][2];
            #pragma unroll
            for (int nt = 0; nt < 8; ++nt) { ps[nt][0] = 0.f; ps[nt][1] = 0.f; }
            #pragma unroll
            for (int mt = 0; mt < 4; ++mt) {
                const float aj0 = adjs[jh * 128 + jm * 64 + mt * 16 + g];
                const float aj8 = adjs[jh * 128 + jm * 64 + mt * 16 + g + 8];
                #pragma unroll
                for (int nt = 0; nt < 8; ++nt) {
                    #pragma unroll
                    for (int c = 0; c < 2; ++c) {
                        const float bv = b2s[hn * 64 + nt * 8 + 2 * tg + c];
                        ps[nt][c] += aj0 * fmaxf(C[mt][nt][c]     + bv, 0.f)
                                   + aj8 * fmaxf(C[mt][nt][2 + c] + bv, 0.f);
                        C[mt][nt][c] = 0.f;
                        C[mt][nt][2 + c] = 0.f;
                    }
                }
            }
            #pragma unroll
            for (int off = 16; off >= 4; off >>= 1)
                #pragma unroll
                for (int nt = 0; nt < 8; ++nt)
                    #pragma unroll
                    for (int c = 0; c < 2; ++c)
                        ps[nt][c] += __shfl_down_sync(0xffffffffu, ps[nt][c], off);
            if (lane < 4) {
                #pragma unroll
                for (int nt = 0; nt < 8; ++nt)
                    #pragma unroll
                    for (int c = 0; c < 2; ++c)
                        part[w * 64 + nt * 8 + 2 * lane + c] = ps[nt][c];
            }
        }
        __syncthreads();
        if ((s & 3) == 3)            // part fully written + synced: fold into acc
            acc += part[(tid >> 6) * 128 + (tid & 63)]
                 + part[(tid >> 6) * 128 + 64 + (tid & 63)];
    }

    agg[row + tid] = acc;
}

// ---------------- tf32 tensor-core GEMM: C = res? res + act(A@W + b) --------
// A:(M,K) row-major, W:(K,N) row-major, C:(M,N). Block tile 64x64, BK=32.
// 128 threads = 4 warps (2m x 2n), warp tile 32m x 32n.
static constexpr int GA = 36;   // A smem stride (32+4)
static constexpr int GW = 68;   // W smem stride (64+4)

__global__ void __launch_bounds__(128)
gemm_tc(const float* __restrict__ A, const float* __restrict__ W,
        const float* __restrict__ bias, const float* __restrict__ res,
        float* __restrict__ Cg, int M, int K, int N, int act)
{
    __shared__ float As[64 * GA];
    __shared__ float Ws[32 * GW];
    const int tid = threadIdx.x, lane = tid & 31, w = tid >> 5;
    const int g = lane >> 2, tg = lane & 3, wm = w & 1, wn = w >> 1;
    const int colB = blockIdx.x * 64, rowB = blockIdx.y * 64;

    float C[2][4][4];
    #pragma unroll
    for (int mt = 0; mt < 2; ++mt)
        #pragma unroll
        for (int nt = 0; nt < 4; ++nt)
            #pragma unroll
            for (int r = 0; r < 4; ++r) C[mt][nt][r] = 0.f;

    for (int k0 = 0; k0 < K; k0 += 32) {
        __syncthreads();
        {   // A fill: 64 rows x 32 k
            const int kq = tid & 7, rr = tid >> 3;
            #pragma unroll
            for (int p = 0; p < 4; ++p) {
                int r = p * 16 + rr, gr = rowB + r, gk = k0 + kq * 4;
                uint4 o = {0u, 0u, 0u, 0u};
                if (gr < M && gk < K) {
                    float4 av = *(const float4*)(A + (size_t)gr * K + gk);
                    o.x = f2tf32(av.x); o.y = f2tf32(av.y);
                    o.z = f2tf32(av.z); o.w = f2tf32(av.w);
                }
                *(uint4*)(As + r * GA + kq * 4) = o;
            }
        }
        {   // W fill: 32 k-rows x 64 n
            const int nq = tid & 15, kr0 = tid >> 4;
            #pragma unroll
            for (int p = 0; p < 4; ++p) {
                int kr = p * 8 + kr0, gk = k0 + kr, gn = colB + nq * 4;
                uint4 o = {0u, 0u, 0u, 0u};
                if (gk < K && gn < N) {
                    float4 wv = *(const float4*)(W + (size_t)gk * N + gn);
                    o.x = f2tf32(wv.x); o.y = f2tf32(wv.y);
                    o.z = f2tf32(wv.z); o.w = f2tf32(wv.w);
                }
                *(uint4*)(Ws + kr * GW + nq * 4) = o;
            }
        }
        __syncthreads();
        const uint32_t* ap = (const uint32_t*)As;
        const uint32_t* wp = (const uint32_t*)Ws;
        #pragma unroll
        for (int ks = 0; ks < 4; ++ks) {
            uint32_t afr[2][4], bfr[4][2];
            #pragma unroll
            for (int mt = 0; mt < 2; ++mt) {
                int r0 = (wm * 32 + mt * 16 + g) * GA + ks * 8;
                afr[mt][0] = ap[r0 + tg];
                afr[mt][1] = ap[r0 + 8 * GA + tg];
                afr[mt][2] = ap[r0 + tg + 4];
                afr[mt][3] = ap[r0 + 8 * GA + tg + 4];
            }
            #pragma unroll
            for (int nt = 0; nt < 4; ++nt) {
                int r0 = (ks * 8 + tg) * GW + wn * 32 + nt * 8 + g;
                bfr[nt][0] = wp[r0];
                bfr[nt][1] = wp[r0 + 4 * GW];
            }
            #pragma unroll
            for (int mt = 0; mt < 2; ++mt)
                #pragma unroll
                for (int nt = 0; nt < 4; ++nt)
                    mma_tf32(C[mt][nt], afr[mt], bfr[nt]);
        }
    }

    #pragma unroll
    for (int mt = 0; mt < 2; ++mt) {
        #pragma unroll
        for (int rh = 0; rh < 2; ++rh) {
            const int m = rowB + wm * 32 + mt * 16 + g + rh * 8;
            if (m < M) {
                #pragma unroll
                for (int nt = 0; nt < 4; ++nt) {
                    #pragma unroll
                    for (int c = 0; c < 2; ++c) {
                        const int n = colB + wn * 32 + nt * 8 + 2 * tg + c;
                        if (n < N) {
                            float v = C[mt][nt][rh * 2 + c] + (bias ? bias[n] : 0.f);
                            if (act) v = fmaxf(v, 0.f);
                            if (res) v += res[(size_t)m * N + n];
                            Cg[(size_t)m * N + n] = v;
                        }
                    }
                }
            }
        }
    }
}

// ---------------- multi-head attention core ---------------------------------
__global__ void attn_kernel(const float* __restrict__ q, int q_bs,
                            const float* __restrict__ k, const float* __restrict__ v,
                            int Lk, float* __restrict__ o)
{
    __shared__ float qs[16 * 32];
    __shared__ float sc[16 * 256];
    const int tid  = threadIdx.x;
    const int head = blockIdx.x;
    const int b    = blockIdx.y;

    const float* qb = q + (size_t)b * q_bs;
    for (int u = tid; u < 512; u += 256) {
        int l = u >> 5, d = u & 31;
        qs[u] = qb[(size_t)l * 256 + head * 32 + d];
    }
    __syncthreads();

    {
        int l = tid & 15, jg = tid >> 4;
        const float* kb = k + ((size_t)b * Lk) * 256 + head * 32;
        for (int j = jg; j < Lk; j += 16) {
            const float* kr = kb + (size_t)j * 256;
            float s = 0.f;
            #pragma unroll
            for (int d = 0; d < 32; ++d) s = fmaf(qs[l * 32 + d], kr[d], s);
            sc[l * 256 + j] = s * 0.0625f;
        }
    }
    __syncthreads();

    if (tid < 16) {
        float m = -1e30f;
        for (int j = 0; j < Lk; ++j) m = fmaxf(m, sc[tid * 256 + j]);
        float sum = 0.f;
        for (int j = 0; j < Lk; ++j) {
            float e = __expf(sc[tid * 256 + j] - m);
            sc[tid * 256 + j] = e;
            sum += e;
        }
        float inv = 1.f / sum;
        for (int j = 0; j < Lk; ++j) sc[tid * 256 + j] *= inv;
    }
    __syncthreads();

    {
        const float* vb = v + ((size_t)b * Lk) * 256 + head * 32;
        for (int u = tid; u < 512; u += 256) {
            int l = u >> 5, d = u & 31;
            float accv = qs[l * 32 + d];
            for (int j = 0; j < Lk; ++j)
                accv = fmaf(sc[l * 256 + j], vb[(size_t)j * 256 + d], accv);
            o[((size_t)(b * 16 + l)) * 256 + head * 32 + d] = accv;
        }
    }
}

// ---------------- host orchestration ---------------------------------------
static inline void launch_tc(const float* A, const float* W, const float* bias,
                             const float* res, float* C, int M, int K, int N, int act)
{
    dim3 grid((N + 63) / 64, (M + 63) / 64);
    gemm_tc<<<grid, 128>>>(A, W, bias, res, C, M, K, N, act);
}

extern "C" void kernel_launch(void* const* d_in, const int* in_sizes, int n_in,
                              void* d_out, int out_size)
{
    (void)in_sizes; (void)n_in; (void)out_size;
    const float* x    = (const float*)d_in[0];
    const float* adj  = (const float*)d_in[1];
    const float* ginW = (const float*)d_in[2];
    const float* ginb = (const float*)d_in[3];
    const float* geW1 = (const float*)d_in[4];
    const float* geb1 = (const float*)d_in[5];
    const float* geW2 = (const float*)d_in[6];
    const float* geb2 = (const float*)d_in[7];
    const float* gnW1 = (const float*)d_in[8];
    const float* gnb1 = (const float*)d_in[9];
    const float* gnW2 = (const float*)d_in[10];
    const float* gnb2 = (const float*)d_in[11];
    const float* goW  = (const float*)d_in[12];
    const float* gob  = (const float*)d_in[13];
    const float* S    = (const float*)d_in[14];
    const float* mWq  = (const float*)d_in[15];
    const float* mbq  = (const float*)d_in[16];
    const float* mWk  = (const float*)d_in[17];
    const float* mbk  = (const float*)d_in[18];
    const float* mWv  = (const float*)d_in[19];
    const float* mbv  = (const float*)d_in[20];
    const float* mWo  = (const float*)d_in[21];
    const float* mbo  = (const float*)d_in[22];
    const float* finW = (const float*)d_in[23];
    const float* finb = (const float*)d_in[24];
    float* out = (float*)d_out;

    float *h, *hi, *hj, *agg, *n1, *n2, *enc, *kb, *vb, *q, *oA, *m1, *m2, *w2t;
    cudaGetSymbolAddress((void**)&h,   g_h);
    cudaGetSymbolAddress((void**)&hi,  g_hi);
    cudaGetSymbolAddress((void**)&hj,  g_hj);
    cudaGetSymbolAddress((void**)&agg, g_agg);
    cudaGetSymbolAddress((void**)&n1,  g_n1);
    cudaGetSymbolAddress((void**)&n2,  g_n2);
    cudaGetSymbolAddress((void**)&enc, g_enc);
    cudaGetSymbolAddress((void**)&kb,  g_k);
    cudaGetSymbolAddress((void**)&vb,  g_v);
    cudaGetSymbolAddress((void**)&q,   g_q);
    cudaGetSymbolAddress((void**)&oA,  g_oA);
    cudaGetSymbolAddress((void**)&m1,  g_m1);
    cudaGetSymbolAddress((void**)&m2,  g_m2);
    cudaGetSymbolAddress((void**)&w2t, g_w2t);

    cudaFuncSetAttribute(edge_mma2, cudaFuncAttributeMaxDynamicSharedMemorySize, EDGE_SMEM_BYTES);

    // 0. prep: transpose+round W2 for the edge GEMM
    prep_w2t<<<256, 256>>>(geW2, w2t);
    // 1. h = x @ gin_W + gin_b          (1024,48)x(48,256)
    launch_tc(x, ginW, ginb, nullptr, h, 1024, 48, 256, 0);
    // 2. hi = h @ Wi ; 3. hj = h @ Wj + geb1
    launch_tc(h, geW1, nullptr, nullptr, hi, 1024, 256, 256, 0);
    launch_tc(h, geW1 + 256 * 256, geb1, nullptr, hj, 1024, 256, 256, 0);
    // 4. fused edge MLP + adjacency contraction -> agg
    edge_mma2<<<dim3(256, 4), 256, EDGE_SMEM_BYTES>>>(hi, hj, w2t, geb2, adj, agg);
    // 5-7. node MLP + encoder
    launch_tc(agg, gnW1, gnb1, nullptr, n1, 1024, 256, 256, 1);
    launch_tc(n1,  gnW2, gnb2, nullptr, n2, 1024, 256, 256, 1);
    launch_tc(n2,  goW,  gob,  nullptr, enc, 1024, 256, 256, 0);

    // ---- MAB 0: Q = broadcast(S), K = enc (Lk=256) ----
    launch_tc(S,   mWq, mbq, nullptr, q,  16,   256, 256, 0);
    launch_tc(enc, mWk, mbk, nullptr, kb, 1024, 256, 256, 0);
    launch_tc(enc, mWv, mbv, nullptr, vb, 1024, 256, 256, 0);
    attn_kernel<<<dim3(8, 4), 256>>>(q, 0, kb, vb, 256, oA);
    launch_tc(oA, mWo, mbo, oA, m1, 64, 256, 256, 1);

    // ---- MAB 1 ----
    launch_tc(m1, mWq + 65536, mbq + 256, nullptr, q,  64, 256, 256, 0);
    launch_tc(m1, mWk + 65536, mbk + 256, nullptr, kb, 64, 256, 256, 0);
    launch_tc(m1, mWv + 65536, mbv + 256, nullptr, vb, 64, 256, 256, 0);
    attn_kernel<<<dim3(8, 4), 256>>>(q, 16 * 256, kb, vb, 16, oA);
    launch_tc(oA, mWo + 65536, mbo + 256, oA, m2, 64, 256, 256, 1);

    // ---- MAB 2 ----
    launch_tc(m2, mWq + 2 * 65536, mbq + 2 * 256, nullptr, q,  64, 256, 256, 0);
    launch_tc(m2, mWk + 2 * 65536, mbk + 2 * 256, nullptr, kb, 64, 256, 256, 0);
    launch_tc(m2, mWv + 2 * 65536, mbv + 2 * 256, nullptr, vb, 64, 256, 256, 0);
    attn_kernel<<<dim3(8, 4), 256>>>(q, 16 * 256, kb, vb, 16, oA);
    launch_tc(oA, mWo + 2 * 65536, mbo + 2 * 256, oA, m1, 64, 256, 256, 1);

    // ---- final: out = m1 @ finW + finb -> (B,16,384) == (B,16,12,32) ----
    launch_tc(m1, finW, finb, nullptr, out, 64, 256, 384, 0);
}

// round 6
// speedup vs baseline: 1.4277x; 1.4277x over previous
#include <cuda_runtime.h>
#include <cuda_bf16.h>
#include <cstdint>
#include <math.h>
#include <stddef.h>

// ---------------- scratch (device globals; no allocations allowed) ----------
__device__ float g_h  [1024 * 256];
__device__ float g_hi [1024 * 256];
__device__ float g_hj [1024 * 256];
__device__ float g_agg[1024 * 256];
__device__ float g_n1 [1024 * 256];
__device__ float g_n2 [1024 * 256];
__device__ float g_enc[1024 * 256];
__device__ float g_k  [1024 * 256];
__device__ float g_v  [1024 * 256];
__device__ float g_q  [64 * 256];
__device__ float g_oA [64 * 256];
__device__ float g_m1 [64 * 256];
__device__ float g_m2 [64 * 256];
__device__ uint32_t g_w2bt[256 * 128];  // W2 transposed+packed: w2bt[n][k/2] = bf16x2(W2[k][n], W2[k+1][n])

// ---------------- helpers ----------------------------------------------------
__device__ __forceinline__ uint32_t pack_bf16x2(float lo, float hi) {
    __nv_bfloat162 p = __floats2bfloat162_rn(lo, hi);   // .x = lo (low 16 bits)
    return *(uint32_t*)&p;
}
// m16n8k16 bf16 MMA (baseline PTX, sm_80+): D = A@B + D, row.col
__device__ __forceinline__ void mma_bf16(float* c, const uint32_t* a, const uint32_t* bf) {
    asm volatile(
        "mma.sync.aligned.m16n8k16.row.col.f32.bf16.bf16.f32 "
        "{%0,%1,%2,%3}, {%4,%5,%6,%7}, {%8,%9}, {%0,%1,%2,%3};"
        : "+f"(c[0]), "+f"(c[1]), "+f"(c[2]), "+f"(c[3])
        : "r"(a[0]), "r"(a[1]), "r"(a[2]), "r"(a[3]), "r"(bf[0]), "r"(bf[1]));
}

// ---------------- prep: W2 (256x256 row-major [k][n]) -> packed bf16 [n][k/2]
__global__ void prep_w2bt(const float* __restrict__ W2, uint32_t* __restrict__ w2bt) {
    int n = blockIdx.x, c = threadIdx.x;    // c = k/2, 0..127
    float f0 = W2[(2 * c) * 256 + n];
    float f1 = W2[(2 * c + 1) * 256 + n];
    w2bt[n * 128 + c] = pack_bf16x2(f0, f1);
}

// ---------------- bf16 mma fused edge-MLP + adjacency contraction ------------
// Per block (i, b, hh): for jh in {0,1}:
//   A[128j,256k] = bf16(relu(hi[b,i,:] + hj[b, jh*128+j, :]))
//   D = A @ W2[:, hh*128 : hh*128+128]
//   acc[h] += sum_j adj[b,i,jh*128+j] * relu(D[j,h] + b2[hh*128+h])
// 256 threads = 8 warps in 2(jm) x 4(hn); warp tile 64j x 32h.
static constexpr int EBS = 36;    // u32 stride (32 data + 4 pad): banks 4g+tg, conflict-free

__global__ void __launch_bounds__(256, 2)
edge_bf16(const float* __restrict__ hi, const float* __restrict__ hjp,
          const uint32_t* __restrict__ w2bt, const float* __restrict__ b2,
          const float* __restrict__ adj, float* __restrict__ agg)
{
    __shared__ float ci[256];
    __shared__ float adjs[256];
    __shared__ float b2s[128];
    __shared__ float part[256];
    __shared__ uint32_t A_s[128 * EBS];
    __shared__ uint32_t W_s[128 * EBS];

    const int tid = threadIdx.x, lane = tid & 31, w = tid >> 5;
    const int i = blockIdx.x, b = blockIdx.y, hh = blockIdx.z;
    const size_t row = (size_t)(b * 256 + i) * 256;

    ci[tid]   = hi[row + tid];
    adjs[tid] = adj[row + tid];
    if (tid < 128) b2s[tid] = b2[hh * 128 + tid];

    const int g  = lane >> 2;        // 0..7
    const int tg = lane & 3;         // 0..3
    const int jm = w & 1;            // warp j-half (64)
    const int hn = w >> 1;           // warp h-tile (32 wide)

    const float* hjb = hjp + (size_t)b * 65536;
    const int kq = tid & 15;         // 16B segment within 64-k chunk
    const int jr = tid >> 4;         // row base 0..15 per fill pass

    float acc = 0.f;                 // tid<128 owns h = tid of this hh-half

    for (int jh = 0; jh < 2; ++jh) {
        float C[4][4][4];
        #pragma unroll
        for (int mt = 0; mt < 4; ++mt)
            #pragma unroll
            for (int nt = 0; nt < 4; ++nt)
                #pragma unroll
                for (int r = 0; r < 4; ++r) C[mt][nt][r] = 0.f;

        for (int kc = 0; kc < 4; ++kc) {
            __syncthreads();   // buffers free (also covers init fills first pass)
            const float4 cv = *(const float4*)(ci + kc * 64 + kq * 4);
            #pragma unroll
            for (int p = 0; p < 8; ++p) {
                const int r = p * 16 + jr;      // 0..127 (j for A, n for W)
                float4 hv = *(const float4*)(hjb + (size_t)(jh * 128 + r) * 256 + kc * 64 + kq * 4);
                uint2 o;
                o.x = pack_bf16x2(fmaxf(cv.x + hv.x, 0.f), fmaxf(cv.y + hv.y, 0.f));
                o.y = pack_bf16x2(fmaxf(cv.z + hv.z, 0.f), fmaxf(cv.w + hv.w, 0.f));
                *(uint2*)(A_s + r * EBS + kq * 2) = o;
                uint2 wv = *(const uint2*)(w2bt + (size_t)(hh * 128 + r) * 128 + kc * 32 + kq * 2);
                *(uint2*)(W_s + r * EBS + kq * 2) = wv;
            }
            __syncthreads();

            #pragma unroll
            for (int ks = 0; ks < 4; ++ks) {    // 4 x K=16 per 64-k chunk
                uint32_t afr[4][4], bfr[4][2];
                #pragma unroll
                for (int mt = 0; mt < 4; ++mt) {
                    int r0 = (jm * 64 + mt * 16 + g) * EBS + ks * 8;
                    afr[mt][0] = A_s[r0 + tg];
                    afr[mt][1] = A_s[r0 + 8 * EBS + tg];
                    afr[mt][2] = A_s[r0 + tg + 4];
                    afr[mt][3] = A_s[r0 + 8 * EBS + tg + 4];
                }
                #pragma unroll
                for (int nt = 0; nt < 4; ++nt) {
                    int r0 = (hn * 32 + nt * 8 + g) * EBS + ks * 8;
                    bfr[nt][0] = W_s[r0 + tg];
                    bfr[nt][1] = W_s[r0 + tg + 4];
                }
                #pragma unroll
                for (int mt = 0; mt < 4; ++mt)
                    #pragma unroll
                    for (int nt = 0; nt < 4; ++nt)
                        mma_bf16(C[mt][nt], afr[mt], bfr[nt]);
            }
        }

        // epilogue for this jh: bias + relu + adj weight, reduce over j
        float ps[4][2];
        #pragma unroll
        for (int nt = 0; nt < 4; ++nt) { ps[nt][0] = 0.f; ps[nt][1] = 0.f; }
        #pragma unroll
        for (int mt = 0; mt < 4; ++mt) {
            const float aj0 = adjs[jh * 128 + jm * 64 + mt * 16 + g];
            const float aj8 = adjs[jh * 128 + jm * 64 + mt * 16 + g + 8];
            #pragma unroll
            for (int nt = 0; nt < 4; ++nt) {
                #pragma unroll
                for (int c = 0; c < 2; ++c) {
                    const float bv = b2s[hn * 32 + nt * 8 + 2 * tg + c];
                    ps[nt][c] += aj0 * fmaxf(C[mt][nt][c]     + bv, 0.f)
                               + aj8 * fmaxf(C[mt][nt][2 + c] + bv, 0.f);
                }
            }
        }
        // reduce over g (lane = 4g+tg): shfl down by 16, 8, 4
        #pragma unroll
        for (int off = 16; off >= 4; off >>= 1)
            #pragma unroll
            for (int nt = 0; nt < 4; ++nt)
                #pragma unroll
                for (int c = 0; c < 2; ++c)
                    ps[nt][c] += __shfl_down_sync(0xffffffffu, ps[nt][c], off);
        if (lane < 4) {
            #pragma unroll
            for (int nt = 0; nt < 4; ++nt)
                #pragma unroll
                for (int c = 0; c < 2; ++c)
                    part[w * 32 + nt * 8 + 2 * lane + c] = ps[nt][c];
        }
        __syncthreads();
        if (tid < 128) {
            const int hn2 = tid >> 5, hl = tid & 31;
            acc += part[(hn2 * 2 + 0) * 32 + hl] + part[(hn2 * 2 + 1) * 32 + hl];
        }
    }

    if (tid < 128) agg[row + hh * 128 + tid] = acc;
}

// ---------------- generic fp32 tiled GEMM: C = res? res + act(A@W + b) ------
__global__ void gemm_kernel(const float* __restrict__ A, const float* __restrict__ W,
                            const float* __restrict__ bias, const float* __restrict__ res,
                            float* __restrict__ C, int M, int K, int N, int act)
{
    __shared__ float As[32 * 33];
    __shared__ float Ws[32 * 33];
    const int tid  = threadIdx.x;
    const int lane = tid & 31;
    const int ty   = tid >> 5;
    const int colB = blockIdx.x * 32;
    const int rowB = blockIdx.y * 32;

    float acc[4] = {0.f, 0.f, 0.f, 0.f};

    for (int k0 = 0; k0 < K; k0 += 32) {
        #pragma unroll
        for (int u = 0; u < 4; ++u) {
            int idx = tid + u * 256;
            int r = idx >> 5, c = idx & 31;
            int gr = rowB + r, gk = k0 + c;
            As[r * 33 + c] = (gr < M && gk < K) ? A[(size_t)gr * K + gk] : 0.f;
            int wk = k0 + r, wc = colB + c;
            Ws[r * 33 + c] = (wk < K && wc < N) ? W[(size_t)wk * N + wc] : 0.f;
        }
        __syncthreads();
        #pragma unroll
        for (int kk = 0; kk < 32; ++kk) {
            float wv = Ws[kk * 33 + lane];
            #pragma unroll
            for (int r = 0; r < 4; ++r)
                acc[r] = fmaf(As[(ty * 4 + r) * 33 + kk], wv, acc[r]);
        }
        __syncthreads();
    }

    int col = colB + lane;
    if (col < N) {
        float bv = bias ? bias[col] : 0.f;
        #pragma unroll
        for (int r = 0; r < 4; ++r) {
            int rowi = rowB + ty * 4 + r;
            if (rowi < M) {
                float v = acc[r] + bv;
                if (act) v = fmaxf(v, 0.f);
                if (res) v += res[(size_t)rowi * N + col];
                C[(size_t)rowi * N + col] = v;
            }
        }
    }
}

// ---------------- multi-head attention core ---------------------------------
__global__ void attn_kernel(const float* __restrict__ q, int q_bs,
                            const float* __restrict__ k, const float* __restrict__ v,
                            int Lk, float* __restrict__ o)
{
    __shared__ float qs[16 * 32];
    __shared__ float sc[16 * 256];
    const int tid  = threadIdx.x;
    const int head = blockIdx.x;
    const int b    = blockIdx.y;

    const float* qb = q + (size_t)b * q_bs;
    for (int u = tid; u < 512; u += 256) {
        int l = u >> 5, d = u & 31;
        qs[u] = qb[(size_t)l * 256 + head * 32 + d];
    }
    __syncthreads();

    {
        int l = tid & 15, jg = tid >> 4;
        const float* kb = k + ((size_t)b * Lk) * 256 + head * 32;
        for (int j = jg; j < Lk; j += 16) {
            const float* kr = kb + (size_t)j * 256;
            float s = 0.f;
            #pragma unroll
            for (int d = 0; d < 32; ++d) s = fmaf(qs[l * 32 + d], kr[d], s);
            sc[l * 256 + j] = s * 0.0625f;
        }
    }
    __syncthreads();

    if (tid < 16) {
        float m = -1e30f;
        for (int j = 0; j < Lk; ++j) m = fmaxf(m, sc[tid * 256 + j]);
        float sum = 0.f;
        for (int j = 0; j < Lk; ++j) {
            float e = __expf(sc[tid * 256 + j] - m);
            sc[tid * 256 + j] = e;
            sum += e;
        }
        float inv = 1.f / sum;
        for (int j = 0; j < Lk; ++j) sc[tid * 256 + j] *= inv;
    }
    __syncthreads();

    {
        const float* vb = v + ((size_t)b * Lk) * 256 + head * 32;
        for (int u = tid; u < 512; u += 256) {
            int l = u >> 5, d = u & 31;
            float accv = qs[l * 32 + d];
            for (int j = 0; j < Lk; ++j)
                accv = fmaf(sc[l * 256 + j], vb[(size_t)j * 256 + d], accv);
            o[((size_t)(b * 16 + l)) * 256 + head * 32 + d] = accv;
        }
    }
}

// ---------------- host orchestration ---------------------------------------
static inline void launch_gemm(const float* A, const float* W, const float* bias,
                               const float* res, float* C, int M, int K, int N, int act)
{
    dim3 grid((N + 31) / 32, (M + 31) / 32);
    gemm_kernel<<<grid, 256>>>(A, W, bias, res, C, M, K, N, act);
}

extern "C" void kernel_launch(void* const* d_in, const int* in_sizes, int n_in,
                              void* d_out, int out_size)
{
    (void)in_sizes; (void)n_in; (void)out_size;
    const float* x    = (const float*)d_in[0];
    const float* adj  = (const float*)d_in[1];
    const float* ginW = (const float*)d_in[2];
    const float* ginb = (const float*)d_in[3];
    const float* geW1 = (const float*)d_in[4];
    const float* geb1 = (const float*)d_in[5];
    const float* geW2 = (const float*)d_in[6];
    const float* geb2 = (const float*)d_in[7];
    const float* gnW1 = (const float*)d_in[8];
    const float* gnb1 = (const float*)d_in[9];
    const float* gnW2 = (const float*)d_in[10];
    const float* gnb2 = (const float*)d_in[11];
    const float* goW  = (const float*)d_in[12];
    const float* gob  = (const float*)d_in[13];
    const float* S    = (const float*)d_in[14];
    const float* mWq  = (const float*)d_in[15];
    const float* mbq  = (const float*)d_in[16];
    const float* mWk  = (const float*)d_in[17];
    const float* mbk  = (const float*)d_in[18];
    const float* mWv  = (const float*)d_in[19];
    const float* mbv  = (const float*)d_in[20];
    const float* mWo  = (const float*)d_in[21];
    const float* mbo  = (const float*)d_in[22];
    const float* finW = (const float*)d_in[23];
    const float* finb = (const float*)d_in[24];
    float* out = (float*)d_out;

    float *h, *hi, *hj, *agg, *n1, *n2, *enc, *kb, *vb, *q, *oA, *m1, *m2;
    uint32_t* w2bt;
    cudaGetSymbolAddress((void**)&h,   g_h);
    cudaGetSymbolAddress((void**)&hi,  g_hi);
    cudaGetSymbolAddress((void**)&hj,  g_hj);
    cudaGetSymbolAddress((void**)&agg, g_agg);
    cudaGetSymbolAddress((void**)&n1,  g_n1);
    cudaGetSymbolAddress((void**)&n2,  g_n2);
    cudaGetSymbolAddress((void**)&enc, g_enc);
    cudaGetSymbolAddress((void**)&kb,  g_k);
    cudaGetSymbolAddress((void**)&vb,  g_v);
    cudaGetSymbolAddress((void**)&q,   g_q);
    cudaGetSymbolAddress((void**)&oA,  g_oA);
    cudaGetSymbolAddress((void**)&m1,  g_m1);
    cudaGetSymbolAddress((void**)&m2,  g_m2);
    cudaGetSymbolAddress((void**)&w2bt, g_w2bt);

    // 0. prep: transpose+pack W2 to bf16 for the edge GEMM
    prep_w2bt<<<256, 128>>>(geW2, w2bt);
    // 1. h = x @ gin_W + gin_b          (1024,48)x(48,256)
    launch_gemm(x, ginW, ginb, nullptr, h, 1024, 48, 256, 0);
    // 2. hi = h @ Wi ; 3. hj = h @ Wj + geb1
    launch_gemm(h, geW1, nullptr, nullptr, hi, 1024, 256, 256, 0);
    launch_gemm(h, geW1 + 256 * 256, geb1, nullptr, hj, 1024, 256, 256, 0);
    // 4. fused edge MLP + adjacency contraction -> agg (bf16 mma.sync)
    edge_bf16<<<dim3(256, 4, 2), 256>>>(hi, hj, w2bt, geb2, adj, agg);
    // 5-7. node MLP + encoder
    launch_gemm(agg, gnW1, gnb1, nullptr, n1, 1024, 256, 256, 1);
    launch_gemm(n1,  gnW2, gnb2, nullptr, n2, 1024, 256, 256, 1);
    launch_gemm(n2,  goW,  gob,  nullptr, enc, 1024, 256, 256, 0);

    // ---- MAB 0: Q = broadcast(S), K = enc (Lk=256) ----
    launch_gemm(S,   mWq, mbq, nullptr, q,  16,   256, 256, 0);
    launch_gemm(enc, mWk, mbk, nullptr, kb, 1024, 256, 256, 0);
    launch_gemm(enc, mWv, mbv, nullptr, vb, 1024, 256, 256, 0);
    attn_kernel<<<dim3(8, 4), 256>>>(q, 0, kb, vb, 256, oA);
    launch_gemm(oA, mWo, mbo, oA, m1, 64, 256, 256, 1);

    // ---- MAB 1 ----
    launch_gemm(m1, mWq + 65536, mbq + 256, nullptr, q,  64, 256, 256, 0);
    launch_gemm(m1, mWk + 65536, mbk + 256, nullptr, kb, 64, 256, 256, 0);
    launch_gemm(m1, mWv + 65536, mbv + 256, nullptr, vb, 64, 256, 256, 0);
    attn_kernel<<<dim3(8, 4), 256>>>(q, 16 * 256, kb, vb, 16, oA);
    launch_gemm(oA, mWo + 65536, mbo + 256, oA, m2, 64, 256, 256, 1);

    // ---- MAB 2 ----
    launch_gemm(m2, mWq + 2 * 65536, mbq + 2 * 256, nullptr, q,  64, 256, 256, 0);
    launch_gemm(m2, mWk + 2 * 65536, mbk + 2 * 256, nullptr, kb, 64, 256, 256, 0);
    launch_gemm(m2, mWv + 2 * 65536, mbv + 2 * 256, nullptr, vb, 64, 256, 256, 0);
    attn_kernel<<<dim3(8, 4), 256>>>(q, 16 * 256, kb, vb, 16, oA);
    launch_gemm(oA, mWo + 2 * 65536, mbo + 2 * 256, oA, m1, 64, 256, 256, 1);

    // ---- final: out = m1 @ finW + finb -> (B,16,384) == (B,16,12,32) ----
    launch_gemm(m1, finW, finb, nullptr, out, 64, 256, 384, 0);
}

// round 7
// speedup vs baseline: 1.6579x; 1.1612x over previous
#include <cuda_runtime.h>
#include <cuda_bf16.h>
#include <cstdint>
#include <math.h>
#include <stddef.h>

// ---------------- scratch (device globals; no allocations allowed) ----------
__device__ float g_h  [1024 * 256];
__device__ float g_hi [1024 * 256];
__device__ float g_hj [1024 * 256];
__device__ float g_agg[1024 * 256];
__device__ float g_n1 [1024 * 256];
__device__ float g_n2 [1024 * 256];
__device__ float g_enc[1024 * 256];
__device__ float g_k  [1024 * 256];
__device__ float g_v  [1024 * 256];
__device__ float g_q  [64 * 256];
__device__ float g_oA [64 * 256];
__device__ float g_m1 [64 * 256];
__device__ float g_m2 [64 * 256];
__device__ uint32_t g_w2bt[256 * 128];  // W2 transposed+packed: w2bt[n][k/2] = bf16x2(W2[k][n], W2[k+1][n])

// ---------------- helpers ----------------------------------------------------
__device__ __forceinline__ uint32_t pack_bf16x2(float lo, float hi) {
    __nv_bfloat162 p = __floats2bfloat162_rn(lo, hi);
    return *(uint32_t*)&p;
}
// m16n8k16 bf16 MMA (baseline PTX, sm_80+): D = A@B + D, row.col
__device__ __forceinline__ void mma_bf16(float* c, const uint32_t* a, const uint32_t* bf) {
    asm volatile(
        "mma.sync.aligned.m16n8k16.row.col.f32.bf16.bf16.f32 "
        "{%0,%1,%2,%3}, {%4,%5,%6,%7}, {%8,%9}, {%0,%1,%2,%3};"
        : "+f"(c[0]), "+f"(c[1]), "+f"(c[2]), "+f"(c[3])
        : "r"(a[0]), "r"(a[1]), "r"(a[2]), "r"(a[3]), "r"(bf[0]), "r"(bf[1]));
}

// ---------------- prep: W2 (256x256 row-major [k][n]) -> packed bf16 [n][k/2]
__global__ void prep_w2bt(const float* __restrict__ W2, uint32_t* __restrict__ w2bt) {
    int n = blockIdx.x, c = threadIdx.x;
    w2bt[n * 128 + c] = pack_bf16x2(W2[(2 * c) * 256 + n], W2[(2 * c + 1) * 256 + n]);
}

// ---------------- edge v3: merged-h, W-cached, double-buffered A -------------
// Per block (i, b): for jh in {0,1}, kc in {0..3}:
//   A[128j x 64k] = bf16(relu(hi[b,i,:] + hj[b, jh*128+j, :]))   (A buf s&1)
//   C += A @ W2slice(kc)  (W cached in 4 bufs, filled during jh=0)
//   per jh: ps += adj-weighted relu(C + b2); single reduce at end.
// 512 threads = 16 warps: jm = w&1 (64j), hn = w>>1 (32h each, 256h total).
static constexpr int EBS = 36;           // u32 row stride (32 data + 4 pad)
static constexpr int EV_A = 128 * EBS;   // one A buf (u32)
static constexpr int EV_W = 256 * EBS;   // one W buf (u32)
static constexpr int EV_U32 = 2 * EV_A + 4 * EV_W;          // 46080
static constexpr int EDGE3_SMEM = (EV_U32 + 1280) * 4;      // + ci/adjs/b2s/part = 189440 B

__global__ void __launch_bounds__(512, 1)
edge_bf16_v3(const float* __restrict__ hi, const float* __restrict__ hjp,
             const uint32_t* __restrict__ w2bt, const float* __restrict__ b2,
             const float* __restrict__ adj, float* __restrict__ agg)
{
    extern __shared__ uint32_t smu[];
    uint32_t* Abufs = smu;                     // [2][128*EBS]
    uint32_t* Wbufs = smu + 2 * EV_A;          // [4][256*EBS]
    float* ci   = (float*)(smu + EV_U32);
    float* adjs = ci + 256;
    float* b2s  = adjs + 256;
    float* part = b2s + 256;                   // 512 floats

    const int tid = threadIdx.x, lane = tid & 31, w = tid >> 5;
    const int i = blockIdx.x, b = blockIdx.y;
    const size_t row = (size_t)(b * 256 + i) * 256;

    if (tid < 256) {
        ci[tid]   = hi[row + tid];
        adjs[tid] = adj[row + tid];
        b2s[tid]  = b2[tid];
    }
    __syncthreads();

    const int g  = lane >> 2;      // 0..7
    const int tg = lane & 3;       // 0..3
    const int jm = w & 1;          // j half (64) of the 128-row pass
    const int hn = w >> 1;         // h tile 0..7 (32 wide)

    const float* hjb = hjp + (size_t)b * 65536;
    const int kq = tid & 15;       // uint2 column within 64-k chunk
    const int jr = tid >> 4;       // 0..31 row base per fill pass

    float C[4][4][4];
    #pragma unroll
    for (int mt = 0; mt < 4; ++mt)
        #pragma unroll
        for (int nt = 0; nt < 4; ++nt)
            #pragma unroll
            for (int r = 0; r < 4; ++r) C[mt][nt][r] = 0.f;
    float ps[4][2];
    #pragma unroll
    for (int nt = 0; nt < 4; ++nt) { ps[nt][0] = 0.f; ps[nt][1] = 0.f; }

    auto fillA = [&](int s) {
        const int jh = s >> 2, kc = s & 3;
        uint32_t* Ab = Abufs + (s & 1) * EV_A;
        const float4 cv = *(const float4*)(ci + kc * 64 + kq * 4);
        #pragma unroll
        for (int p = 0; p < 4; ++p) {
            const int r = p * 32 + jr;
            float4 hv = *(const float4*)(hjb + (size_t)(jh * 128 + r) * 256 + kc * 64 + kq * 4);
            uint2 o;
            o.x = pack_bf16x2(fmaxf(cv.x + hv.x, 0.f), fmaxf(cv.y + hv.y, 0.f));
            o.y = pack_bf16x2(fmaxf(cv.z + hv.z, 0.f), fmaxf(cv.w + hv.w, 0.f));
            *(uint2*)(Ab + r * EBS + kq * 2) = o;
        }
    };
    auto fillW = [&](int kc) {
        uint32_t* Wb = Wbufs + kc * EV_W;
        #pragma unroll
        for (int p = 0; p < 8; ++p) {
            const int r = p * 32 + jr;
            uint2 wv = *(const uint2*)(w2bt + (size_t)r * 128 + kc * 32 + kq * 2);
            *(uint2*)(Wb + r * EBS + kq * 2) = wv;
        }
    };

    fillA(0);
    fillW(0);
    __syncthreads();

    for (int s = 0; s < 8; ++s) {
        // ---- MMA on buffer s (issued first so fill LDGs hide behind it) ----
        const uint32_t* Ab = Abufs + (s & 1) * EV_A;
        const uint32_t* Wb = Wbufs + (s & 3) * EV_W;
        #pragma unroll
        for (int ks = 0; ks < 4; ++ks) {
            uint32_t afr[4][4], bfr[4][2];
            #pragma unroll
            for (int mt = 0; mt < 4; ++mt) {
                int r0 = (jm * 64 + mt * 16 + g) * EBS + ks * 8;
                afr[mt][0] = Ab[r0 + tg];
                afr[mt][1] = Ab[r0 + 8 * EBS + tg];
                afr[mt][2] = Ab[r0 + tg + 4];
                afr[mt][3] = Ab[r0 + 8 * EBS + tg + 4];
            }
            #pragma unroll
            for (int nt = 0; nt < 4; ++nt) {
                int r0 = (hn * 32 + nt * 8 + g) * EBS + ks * 8;
                bfr[nt][0] = Wb[r0 + tg];
                bfr[nt][1] = Wb[r0 + tg + 4];
            }
            #pragma unroll
            for (int mt = 0; mt < 4; ++mt)
                #pragma unroll
                for (int nt = 0; nt < 4; ++nt)
                    mma_bf16(C[mt][nt], afr[mt], bfr[nt]);
        }
        // ---- prefetch next buffers ----
        if (s < 7) {
            fillA(s + 1);
            if (s < 3) fillW(s + 1);
        }
        // ---- end of a jh pass: fold C into adj-weighted per-lane partials ----
        if ((s & 3) == 3) {
            const int jh = s >> 2;
            #pragma unroll
            for (int mt = 0; mt < 4; ++mt) {
                const float aj0 = adjs[jh * 128 + jm * 64 + mt * 16 + g];
                const float aj8 = adjs[jh * 128 + jm * 64 + mt * 16 + g + 8];
                #pragma unroll
                for (int nt = 0; nt < 4; ++nt) {
                    #pragma unroll
                    for (int c = 0; c < 2; ++c) {
                        const float bv = b2s[hn * 32 + nt * 8 + 2 * tg + c];
                        ps[nt][c] += aj0 * fmaxf(C[mt][nt][c]     + bv, 0.f)
                                   + aj8 * fmaxf(C[mt][nt][2 + c] + bv, 0.f);
                        C[mt][nt][c] = 0.f;
                        C[mt][nt][2 + c] = 0.f;
                    }
                }
            }
        }
        __syncthreads();
    }

    // ---- final reduce over g (lane = 4g+tg), combine jm halves, store ------
    #pragma unroll
    for (int off = 16; off >= 4; off >>= 1)
        #pragma unroll
        for (int nt = 0; nt < 4; ++nt)
            #pragma unroll
            for (int c = 0; c < 2; ++c)
                ps[nt][c] += __shfl_down_sync(0xffffffffu, ps[nt][c], off);
    if (lane < 4) {
        #pragma unroll
        for (int nt = 0; nt < 4; ++nt)
            #pragma unroll
            for (int c = 0; c < 2; ++c)
                part[w * 32 + nt * 8 + 2 * lane + c] = ps[nt][c];
    }
    __syncthreads();
    if (tid < 256) {
        const int hq = tid >> 5, hl = tid & 31;
        agg[row + tid] = part[(2 * hq) * 32 + hl] + part[(2 * hq + 1) * 32 + hl];
    }
}

// ---------------- generic fp32 tiled GEMM: C = res? res + act(A@W + b) ------
__global__ void gemm_kernel(const float* __restrict__ A, const float* __restrict__ W,
                            const float* __restrict__ bias, const float* __restrict__ res,
                            float* __restrict__ C, int M, int K, int N, int act)
{
    __shared__ float As[32 * 33];
    __shared__ float Ws[32 * 33];
    const int tid  = threadIdx.x;
    const int lane = tid & 31;
    const int ty   = tid >> 5;
    const int colB = blockIdx.x * 32;
    const int rowB = blockIdx.y * 32;

    float acc[4] = {0.f, 0.f, 0.f, 0.f};

    for (int k0 = 0; k0 < K; k0 += 32) {
        #pragma unroll
        for (int u = 0; u < 4; ++u) {
            int idx = tid + u * 256;
            int r = idx >> 5, c = idx & 31;
            int gr = rowB + r, gk = k0 + c;
            As[r * 33 + c] = (gr < M && gk < K) ? A[(size_t)gr * K + gk] : 0.f;
            int wk = k0 + r, wc = colB + c;
            Ws[r * 33 + c] = (wk < K && wc < N) ? W[(size_t)wk * N + wc] : 0.f;
        }
        __syncthreads();
        #pragma unroll
        for (int kk = 0; kk < 32; ++kk) {
            float wv = Ws[kk * 33 + lane];
            #pragma unroll
            for (int r = 0; r < 4; ++r)
                acc[r] = fmaf(As[(ty * 4 + r) * 33 + kk], wv, acc[r]);
        }
        __syncthreads();
    }

    int col = colB + lane;
    if (col < N) {
        float bv = bias ? bias[col] : 0.f;
        #pragma unroll
        for (int r = 0; r < 4; ++r) {
            int rowi = rowB + ty * 4 + r;
            if (rowi < M) {
                float v = acc[r] + bv;
                if (act) v = fmaxf(v, 0.f);
                if (res) v += res[(size_t)rowi * N + col];
                C[(size_t)rowi * N + col] = v;
            }
        }
    }
}

// ---------------- fused multi-weight GEMM (K=N=256, M % 32 == 0) ------------
// grid.x = 8 * nmats; block (bx>>3) selects (W, bias, C) triple.
__global__ void gemm_qkv(const float* __restrict__ A,
                         const float* __restrict__ W0, const float* __restrict__ W1,
                         const float* __restrict__ W2,
                         const float* __restrict__ b0, const float* __restrict__ b1,
                         const float* __restrict__ b2,
                         float* __restrict__ C0, float* __restrict__ C1,
                         float* __restrict__ C2)
{
    __shared__ float As[32 * 33];
    __shared__ float Ws[32 * 33];
    const int tid = threadIdx.x, lane = tid & 31, ty = tid >> 5;
    const int sel  = blockIdx.x >> 3;
    const int colB = (blockIdx.x & 7) * 32;
    const int rowB = blockIdx.y * 32;
    const float* W    = sel == 0 ? W0 : (sel == 1 ? W1 : W2);
    const float* bias = sel == 0 ? b0 : (sel == 1 ? b1 : b2);
    float*       C    = sel == 0 ? C0 : (sel == 1 ? C1 : C2);

    float acc[4] = {0.f, 0.f, 0.f, 0.f};
    for (int k0 = 0; k0 < 256; k0 += 32) {
        #pragma unroll
        for (int u = 0; u < 4; ++u) {
            int idx = tid + u * 256;
            int r = idx >> 5, c = idx & 31;
            As[r * 33 + c] = A[(size_t)(rowB + r) * 256 + k0 + c];
            Ws[r * 33 + c] = W[(size_t)(k0 + r) * 256 + colB + c];
        }
        __syncthreads();
        #pragma unroll
        for (int kk = 0; kk < 32; ++kk) {
            float wv = Ws[kk * 33 + lane];
            #pragma unroll
            for (int r = 0; r < 4; ++r)
                acc[r] = fmaf(As[(ty * 4 + r) * 33 + kk], wv, acc[r]);
        }
        __syncthreads();
    }
    const int col = colB + lane;
    const float bv = bias ? bias[col] : 0.f;
    #pragma unroll
    for (int r = 0; r < 4; ++r)
        C[(size_t)(rowB + ty * 4 + r) * 256 + col] = acc[r] + bv;
}

// ---------------- multi-head attention core ---------------------------------
__global__ void attn_kernel(const float* __restrict__ q, int q_bs,
                            const float* __restrict__ k, const float* __restrict__ v,
                            int Lk, float* __restrict__ o)
{
    __shared__ float qs[16 * 32];
    __shared__ float sc[16 * 256];
    const int tid  = threadIdx.x;
    const int head = blockIdx.x;
    const int b    = blockIdx.y;

    const float* qb = q + (size_t)b * q_bs;
    for (int u = tid; u < 512; u += 256) {
        int l = u >> 5, d = u & 31;
        qs[u] = qb[(size_t)l * 256 + head * 32 + d];
    }
    __syncthreads();

    {
        int l = tid & 15, jg = tid >> 4;
        const float* kb = k + ((size_t)b * Lk) * 256 + head * 32;
        for (int j = jg; j < Lk; j += 16) {
            const float* kr = kb + (size_t)j * 256;
            float s = 0.f;
            #pragma unroll
            for (int d = 0; d < 32; ++d) s = fmaf(qs[l * 32 + d], kr[d], s);
            sc[l * 256 + j] = s * 0.0625f;
        }
    }
    __syncthreads();

    if (tid < 16) {
        float m = -1e30f;
        for (int j = 0; j < Lk; ++j) m = fmaxf(m, sc[tid * 256 + j]);
        float sum = 0.f;
        for (int j = 0; j < Lk; ++j) {
            float e = __expf(sc[tid * 256 + j] - m);
            sc[tid * 256 + j] = e;
            sum += e;
        }
        float inv = 1.f / sum;
        for (int j = 0; j < Lk; ++j) sc[tid * 256 + j] *= inv;
    }
    __syncthreads();

    {
        const float* vb = v + ((size_t)b * Lk) * 256 + head * 32;
        for (int u = tid; u < 512; u += 256) {
            int l = u >> 5, d = u & 31;
            float accv = qs[l * 32 + d];
            for (int j = 0; j < Lk; ++j)
                accv = fmaf(sc[l * 256 + j], vb[(size_t)j * 256 + d], accv);
            o[((size_t)(b * 16 + l)) * 256 + head * 32 + d] = accv;
        }
    }
}

// ---------------- host orchestration ---------------------------------------
static inline void launch_gemm(const float* A, const float* W, const float* bias,
                               const float* res, float* C, int M, int K, int N, int act)
{
    dim3 grid((N + 31) / 32, (M + 31) / 32);
    gemm_kernel<<<grid, 256>>>(A, W, bias, res, C, M, K, N, act);
}

extern "C" void kernel_launch(void* const* d_in, const int* in_sizes, int n_in,
                              void* d_out, int out_size)
{
    (void)in_sizes; (void)n_in; (void)out_size;
    const float* x    = (const float*)d_in[0];
    const float* adj  = (const float*)d_in[1];
    const float* ginW = (const float*)d_in[2];
    const float* ginb = (const float*)d_in[3];
    const float* geW1 = (const float*)d_in[4];
    const float* geb1 = (const float*)d_in[5];
    const float* geW2 = (const float*)d_in[6];
    const float* geb2 = (const float*)d_in[7];
    const float* gnW1 = (const float*)d_in[8];
    const float* gnb1 = (const float*)d_in[9];
    const float* gnW2 = (const float*)d_in[10];
    const float* gnb2 = (const float*)d_in[11];
    const float* goW  = (const float*)d_in[12];
    const float* gob  = (const float*)d_in[13];
    const float* S    = (const float*)d_in[14];
    const float* mWq  = (const float*)d_in[15];
    const float* mbq  = (const float*)d_in[16];
    const float* mWk  = (const float*)d_in[17];
    const float* mbk  = (const float*)d_in[18];
    const float* mWv  = (const float*)d_in[19];
    const float* mbv  = (const float*)d_in[20];
    const float* mWo  = (const float*)d_in[21];
    const float* mbo  = (const float*)d_in[22];
    const float* finW = (const float*)d_in[23];
    const float* finb = (const float*)d_in[24];
    float* out = (float*)d_out;

    float *h, *hi, *hj, *agg, *n1, *n2, *enc, *kb, *vb, *q, *oA, *m1, *m2;
    uint32_t* w2bt;
    cudaGetSymbolAddress((void**)&h,   g_h);
    cudaGetSymbolAddress((void**)&hi,  g_hi);
    cudaGetSymbolAddress((void**)&hj,  g_hj);
    cudaGetSymbolAddress((void**)&agg, g_agg);
    cudaGetSymbolAddress((void**)&n1,  g_n1);
    cudaGetSymbolAddress((void**)&n2,  g_n2);
    cudaGetSymbolAddress((void**)&enc, g_enc);
    cudaGetSymbolAddress((void**)&kb,  g_k);
    cudaGetSymbolAddress((void**)&vb,  g_v);
    cudaGetSymbolAddress((void**)&q,   g_q);
    cudaGetSymbolAddress((void**)&oA,  g_oA);
    cudaGetSymbolAddress((void**)&m1,  g_m1);
    cudaGetSymbolAddress((void**)&m2,  g_m2);
    cudaGetSymbolAddress((void**)&w2bt, g_w2bt);

    cudaFuncSetAttribute(edge_bf16_v3, cudaFuncAttributeMaxDynamicSharedMemorySize, EDGE3_SMEM);

    // 0. prep: transpose+pack W2 to bf16
    prep_w2bt<<<256, 128>>>(geW2, w2bt);
    // 1. h = x @ gin_W + gin_b
    launch_gemm(x, ginW, ginb, nullptr, h, 1024, 48, 256, 0);
    // 2+3. hi = h @ Wi ; hj = h @ Wj + geb1 (one fused launch)
    gemm_qkv<<<dim3(16, 32), 256>>>(h, geW1, geW1 + 65536, nullptr,
                                    nullptr, geb1, nullptr, hi, hj, nullptr);
    // 4. fused edge MLP + adjacency contraction -> agg
    edge_bf16_v3<<<dim3(256, 4), 512, EDGE3_SMEM>>>(hi, hj, w2bt, geb2, adj, agg);
    // 5-7. node MLP + encoder
    launch_gemm(agg, gnW1, gnb1, nullptr, n1, 1024, 256, 256, 1);
    launch_gemm(n1,  gnW2, gnb2, nullptr, n2, 1024, 256, 256, 1);
    launch_gemm(n2,  goW,  gob,  nullptr, enc, 1024, 256, 256, 0);

    // ---- MAB 0: Q = broadcast(S), K = enc (Lk=256) ----
    launch_gemm(S, mWq, mbq, nullptr, q, 16, 256, 256, 0);
    gemm_qkv<<<dim3(16, 32), 256>>>(enc, mWk, mWv, nullptr,
                                    mbk, mbv, nullptr, kb, vb, nullptr);
    attn_kernel<<<dim3(8, 4), 256>>>(q, 0, kb, vb, 256, oA);
    launch_gemm(oA, mWo, mbo, oA, m1, 64, 256, 256, 1);

    // ---- MAB 1 ----
    gemm_qkv<<<dim3(24, 2), 256>>>(m1, mWq + 65536, mWk + 65536, mWv + 65536,
                                   mbq + 256, mbk + 256, mbv + 256, q, kb, vb);
    attn_kernel<<<dim3(8, 4), 256>>>(q, 16 * 256, kb, vb, 16, oA);
    launch_gemm(oA, mWo + 65536, mbo + 256, oA, m2, 64, 256, 256, 1);

    // ---- MAB 2 ----
    gemm_qkv<<<dim3(24, 2), 256>>>(m2, mWq + 2 * 65536, mWk + 2 * 65536, mWv + 2 * 65536,
                                   mbq + 2 * 256, mbk + 2 * 256, mbv + 2 * 256, q, kb, vb);
    attn_kernel<<<dim3(8, 4), 256>>>(q, 16 * 256, kb, vb, 16, oA);
    launch_gemm(oA, mWo + 2 * 65536, mbo + 2 * 256, oA, m1, 64, 256, 256, 1);

    // ---- final: out = m1 @ finW + finb -> (B,16,384) == (B,16,12,32) ----
    launch_gemm(m1, finW, finb, nullptr, out, 64, 256, 384, 0);
}

// round 8
// speedup vs baseline: 1.7670x; 1.0658x over previous
#include <cuda_runtime.h>
#include <cuda_bf16.h>
#include <cstdint>
#include <math.h>
#include <stddef.h>

// ---------------- scratch (device globals; no allocations allowed) ----------
__device__ float g_h  [1024 * 256];
__device__ float g_hi [1024 * 256];
__device__ float g_hj [1024 * 256];
__device__ float g_agg[1024 * 256];
__device__ float g_n1 [1024 * 256];
__device__ float g_n2 [1024 * 256];
__device__ float g_enc[1024 * 256];
__device__ float g_k  [1024 * 256];
__device__ float g_v  [1024 * 256];
__device__ float g_q  [64 * 256];
__device__ float g_oA [64 * 256];
__device__ float g_m1 [64 * 256];
__device__ float g_m2 [64 * 256];
__device__ uint32_t g_w2bt[256 * 128];  // W2 transposed+packed: w2bt[n][k/2] = bf16x2(W2[k][n], W2[k+1][n])

// ---------------- helpers ----------------------------------------------------
__device__ __forceinline__ uint32_t pack_bf16x2(float lo, float hi) {
    __nv_bfloat162 p = __floats2bfloat162_rn(lo, hi);
    return *(uint32_t*)&p;
}
// m16n8k16 bf16 MMA (baseline PTX, sm_80+): D = A@B + D, row.col
__device__ __forceinline__ void mma_bf16(float* c, const uint32_t* a, const uint32_t* bf) {
    asm volatile(
        "mma.sync.aligned.m16n8k16.row.col.f32.bf16.bf16.f32 "
        "{%0,%1,%2,%3}, {%4,%5,%6,%7}, {%8,%9}, {%0,%1,%2,%3};"
        : "+f"(c[0]), "+f"(c[1]), "+f"(c[2]), "+f"(c[3])
        : "r"(a[0]), "r"(a[1]), "r"(a[2]), "r"(a[3]), "r"(bf[0]), "r"(bf[1]));
}
__device__ __forceinline__ void ldsm_x4(uint32_t* r, uint32_t saddr) {
    asm volatile("ldmatrix.sync.aligned.m8n8.x4.shared.b16 {%0,%1,%2,%3}, [%4];"
        : "=r"(r[0]), "=r"(r[1]), "=r"(r[2]), "=r"(r[3]) : "r"(saddr));
}
__device__ __forceinline__ void ldsm_x2(uint32_t* r, uint32_t saddr) {
    asm volatile("ldmatrix.sync.aligned.m8n8.x2.shared.b16 {%0,%1}, [%2];"
        : "=r"(r[0]), "=r"(r[1]) : "r"(saddr));
}

// ---------------- prep: W2 (256x256 row-major [k][n]) -> packed bf16 [n][k/2]
__global__ void prep_w2bt(const float* __restrict__ W2, uint32_t* __restrict__ w2bt) {
    int n = blockIdx.x, c = threadIdx.x;
    w2bt[n * 128 + c] = pack_bf16x2(W2[(2 * c) * 256 + n], W2[(2 * c + 1) * 256 + n]);
}

// ---------------- edge v4: v3 + ldmatrix fragments + L1 prefetch -------------
// Per block (i, b): for jh in {0,1}, kc in {0..3}:
//   A[128j x 64k] = bf16(relu(hi[b,i,:] + hj[b, jh*128+j, :]))   (A buf s&1)
//   C += A @ W2slice(kc)  (W cached in 4 bufs, filled during jh=0)
//   per jh: ps += adj-weighted relu(C + b2); single reduce at end.
// 512 threads = 16 warps: jm = w&1 (64j), hn = w>>1 (32h each, 256h total).
static constexpr int EBS = 36;           // u32 row stride (32 data + 4 pad)
static constexpr int EV_A = 128 * EBS;   // one A buf (u32)
static constexpr int EV_W = 256 * EBS;   // one W buf (u32)
static constexpr int EV_U32 = 2 * EV_A + 4 * EV_W;          // 46080
static constexpr int EDGE3_SMEM = (EV_U32 + 1280) * 4;      // + ci/adjs/b2s/part = 189440 B

__global__ void __launch_bounds__(512, 1)
edge_bf16_v4(const float* __restrict__ hi, const float* __restrict__ hjp,
             const uint32_t* __restrict__ w2bt, const float* __restrict__ b2,
             const float* __restrict__ adj, float* __restrict__ agg)
{
    extern __shared__ uint32_t smu[];
    uint32_t* Abufs = smu;                     // [2][128*EBS]
    uint32_t* Wbufs = smu + 2 * EV_A;          // [4][256*EBS]
    float* ci   = (float*)(smu + EV_U32);
    float* adjs = ci + 256;
    float* b2s  = adjs + 256;
    float* part = b2s + 256;                   // 512 floats

    const int tid = threadIdx.x, lane = tid & 31, w = tid >> 5;
    const int i = blockIdx.x, b = blockIdx.y;
    const size_t row = (size_t)(b * 256 + i) * 256;

    if (tid < 256) {
        ci[tid]   = hi[row + tid];
        adjs[tid] = adj[row + tid];
        b2s[tid]  = b2[tid];
    }
    __syncthreads();

    const int g  = lane >> 2;      // 0..7
    const int tg = lane & 3;       // 0..3
    const int jm = w & 1;          // j half (64) of the 128-row pass
    const int hn = w >> 1;         // h tile 0..7 (32 wide)

    const float* hjb = hjp + (size_t)b * 65536;
    const int kq = tid & 15;       // uint2 column within 64-k chunk
    const int jr = tid >> 4;       // 0..31 row base per fill pass

    // ldmatrix per-thread byte offsets (EBS*4 = 144 B row pitch)
    const uint32_t smemS = (uint32_t)__cvta_generic_to_shared(smu);
    const uint32_t aTh = (uint32_t)((jm * 64 + (lane & 15)) * 144 + (lane >> 4) * 16);
    const uint32_t wTh = (uint32_t)((hn * 32 + (lane & 7)) * 144 + ((lane >> 3) & 1) * 16);

    float C[4][4][4];
    #pragma unroll
    for (int mt = 0; mt < 4; ++mt)
        #pragma unroll
        for (int nt = 0; nt < 4; ++nt)
            #pragma unroll
            for (int r = 0; r < 4; ++r) C[mt][nt][r] = 0.f;
    float ps[4][2];
    #pragma unroll
    for (int nt = 0; nt < 4; ++nt) { ps[nt][0] = 0.f; ps[nt][1] = 0.f; }

    auto fillA = [&](int s) {
        const int jh = (s >> 2) & 1, kc = s & 3;
        uint32_t* Ab = Abufs + (s & 1) * EV_A;
        const float4 cv = *(const float4*)(ci + kc * 64 + kq * 4);
        #pragma unroll
        for (int p = 0; p < 4; ++p) {
            const int r = p * 32 + jr;
            float4 hv = *(const float4*)(hjb + (size_t)(jh * 128 + r) * 256 + kc * 64 + kq * 4);
            uint2 o;
            o.x = pack_bf16x2(fmaxf(cv.x + hv.x, 0.f), fmaxf(cv.y + hv.y, 0.f));
            o.y = pack_bf16x2(fmaxf(cv.z + hv.z, 0.f), fmaxf(cv.w + hv.w, 0.f));
            *(uint2*)(Ab + r * EBS + kq * 2) = o;
        }
    };
    auto prefA = [&](int s) {
        const int jh = (s >> 2) & 1, kc = s & 3;
        #pragma unroll
        for (int p = 0; p < 4; ++p) {
            const int r = p * 32 + jr;
            asm volatile("prefetch.global.L1 [%0];"
                :: "l"(hjb + (size_t)(jh * 128 + r) * 256 + kc * 64 + kq * 4));
        }
    };
    auto fillW = [&](int kc) {
        uint32_t* Wb = Wbufs + kc * EV_W;
        #pragma unroll
        for (int p = 0; p < 8; ++p) {
            const int r = p * 32 + jr;
            uint2 wv = *(const uint2*)(w2bt + (size_t)r * 128 + kc * 32 + kq * 2);
            *(uint2*)(Wb + r * EBS + kq * 2) = wv;
        }
    };

    fillA(0);
    fillW(0);
    __syncthreads();

    for (int s = 0; s < 8; ++s) {
        // prefetch next step's hj lines into L1 (no regs, no stall)
        if (s < 7) prefA(s + 1);

        // ---- MMA on buffer s (ldmatrix fragment loads) ----
        const uint32_t AbS = smemS + (uint32_t)((s & 1) * EV_A * 4) + aTh;
        const uint32_t WbS = smemS + (uint32_t)((2 * EV_A + (s & 3) * EV_W) * 4) + wTh;
        #pragma unroll
        for (int ks = 0; ks < 4; ++ks) {
            uint32_t afr[4][4], bfr[4][2];
            #pragma unroll
            for (int mt = 0; mt < 4; ++mt)
                ldsm_x4(afr[mt], AbS + mt * 2304 + ks * 32);
            #pragma unroll
            for (int nt = 0; nt < 4; ++nt)
                ldsm_x2(bfr[nt], WbS + nt * 1152 + ks * 32);
            #pragma unroll
            for (int mt = 0; mt < 4; ++mt)
                #pragma unroll
                for (int nt = 0; nt < 4; ++nt)
                    mma_bf16(C[mt][nt], afr[mt], bfr[nt]);
        }
        // ---- fill next buffers (LDGs now L1-hot from the prefetch) ----
        if (s < 7) {
            fillA(s + 1);
            if (s < 3) fillW(s + 1);
        }
        // ---- end of a jh pass: fold C into adj-weighted per-lane partials ----
        if ((s & 3) == 3) {
            const int jh = s >> 2;
            #pragma unroll
            for (int mt = 0; mt < 4; ++mt) {
                const float aj0 = adjs[jh * 128 + jm * 64 + mt * 16 + g];
                const float aj8 = adjs[jh * 128 + jm * 64 + mt * 16 + g + 8];
                #pragma unroll
                for (int nt = 0; nt < 4; ++nt) {
                    #pragma unroll
                    for (int c = 0; c < 2; ++c) {
                        const float bv = b2s[hn * 32 + nt * 8 + 2 * tg + c];
                        ps[nt][c] += aj0 * fmaxf(C[mt][nt][c]     + bv, 0.f)
                                   + aj8 * fmaxf(C[mt][nt][2 + c] + bv, 0.f);
                        C[mt][nt][c] = 0.f;
                        C[mt][nt][2 + c] = 0.f;
                    }
                }
            }
        }
        __syncthreads();
    }

    // ---- final reduce over g (lane = 4g+tg), combine jm halves, store ------
    #pragma unroll
    for (int off = 16; off >= 4; off >>= 1)
        #pragma unroll
        for (int nt = 0; nt < 4; ++nt)
            #pragma unroll
            for (int c = 0; c < 2; ++c)
                ps[nt][c] += __shfl_down_sync(0xffffffffu, ps[nt][c], off);
    if (lane < 4) {
        #pragma unroll
        for (int nt = 0; nt < 4; ++nt)
            #pragma unroll
            for (int c = 0; c < 2; ++c)
                part[w * 32 + nt * 8 + 2 * lane + c] = ps[nt][c];
    }
    __syncthreads();
    if (tid < 256) {
        const int hq = tid >> 5, hl = tid & 31;
        agg[row + tid] = part[(2 * hq) * 32 + hl] + part[(2 * hq + 1) * 32 + hl];
    }
}

// ---------------- fp32 tiled GEMM, register double-buffered -----------------
__global__ void gemm_kernel(const float* __restrict__ A, const float* __restrict__ W,
                            const float* __restrict__ bias, const float* __restrict__ res,
                            float* __restrict__ C, int M, int K, int N, int act)
{
    __shared__ float As[32 * 33];
    __shared__ float Ws[32 * 33];
    const int tid  = threadIdx.x;
    const int lane = tid & 31;
    const int ty   = tid >> 5;
    const int colB = blockIdx.x * 32;
    const int rowB = blockIdx.y * 32;

    float acc[4] = {0.f, 0.f, 0.f, 0.f};
    float pa[4], pw[4];
    int rr[4], cc[4];
    #pragma unroll
    for (int u = 0; u < 4; ++u) { int idx = tid + u * 256; rr[u] = idx >> 5; cc[u] = idx & 31; }

    // prologue: load k-tile 0
    #pragma unroll
    for (int u = 0; u < 4; ++u) {
        int gr = rowB + rr[u], gk = cc[u];
        pa[u] = (gr < M && gk < K) ? A[(size_t)gr * K + gk] : 0.f;
        int wk = rr[u], wc = colB + cc[u];
        pw[u] = (wk < K && wc < N) ? W[(size_t)wk * N + wc] : 0.f;
    }

    for (int k0 = 0; k0 < K; k0 += 32) {
        #pragma unroll
        for (int u = 0; u < 4; ++u) {
            As[rr[u] * 33 + cc[u]] = pa[u];
            Ws[rr[u] * 33 + cc[u]] = pw[u];
        }
        __syncthreads();
        const int k1 = k0 + 32;
        if (k1 < K) {   // prefetch next tile; latency hidden under FMA loop
            #pragma unroll
            for (int u = 0; u < 4; ++u) {
                int gr = rowB + rr[u], gk = k1 + cc[u];
                pa[u] = (gr < M && gk < K) ? A[(size_t)gr * K + gk] : 0.f;
                int wk = k1 + rr[u], wc = colB + cc[u];
                pw[u] = (wk < K && wc < N) ? W[(size_t)wk * N + wc] : 0.f;
            }
        }
        #pragma unroll
        for (int kk = 0; kk < 32; ++kk) {
            float wv = Ws[kk * 33 + lane];
            #pragma unroll
            for (int r = 0; r < 4; ++r)
                acc[r] = fmaf(As[(ty * 4 + r) * 33 + kk], wv, acc[r]);
        }
        __syncthreads();
    }

    int col = colB + lane;
    if (col < N) {
        float bv = bias ? bias[col] : 0.f;
        #pragma unroll
        for (int r = 0; r < 4; ++r) {
            int rowi = rowB + ty * 4 + r;
            if (rowi < M) {
                float v = acc[r] + bv;
                if (act) v = fmaxf(v, 0.f);
                if (res) v += res[(size_t)rowi * N + col];
                C[(size_t)rowi * N + col] = v;
            }
        }
    }
}

// ---------------- fused multi-weight GEMM (K=N=256, M % 32 == 0) ------------
// grid.x = 8 * nmats; block (bx>>3) selects (W, bias, C) triple.
__global__ void gemm_qkv(const float* __restrict__ A,
                         const float* __restrict__ W0, const float* __restrict__ W1,
                         const float* __restrict__ W2,
                         const float* __restrict__ b0, const float* __restrict__ b1,
                         const float* __restrict__ b2,
                         float* __restrict__ C0, float* __restrict__ C1,
                         float* __restrict__ C2)
{
    __shared__ float As[32 * 33];
    __shared__ float Ws[32 * 33];
    const int tid = threadIdx.x, lane = tid & 31, ty = tid >> 5;
    const int sel  = blockIdx.x >> 3;
    const int colB = (blockIdx.x & 7) * 32;
    const int rowB = blockIdx.y * 32;
    const float* W    = sel == 0 ? W0 : (sel == 1 ? W1 : W2);
    const float* bias = sel == 0 ? b0 : (sel == 1 ? b1 : b2);
    float*       C    = sel == 0 ? C0 : (sel == 1 ? C1 : C2);

    float acc[4] = {0.f, 0.f, 0.f, 0.f};
    float pa[4], pw[4];
    int rr[4], cc[4];
    #pragma unroll
    for (int u = 0; u < 4; ++u) { int idx = tid + u * 256; rr[u] = idx >> 5; cc[u] = idx & 31; }
    #pragma unroll
    for (int u = 0; u < 4; ++u) {
        pa[u] = A[(size_t)(rowB + rr[u]) * 256 + cc[u]];
        pw[u] = W[(size_t)rr[u] * 256 + colB + cc[u]];
    }

    for (int k0 = 0; k0 < 256; k0 += 32) {
        #pragma unroll
        for (int u = 0; u < 4; ++u) {
            As[rr[u] * 33 + cc[u]] = pa[u];
            Ws[rr[u] * 33 + cc[u]] = pw[u];
        }
        __syncthreads();
        const int k1 = k0 + 32;
        if (k1 < 256) {
            #pragma unroll
            for (int u = 0; u < 4; ++u) {
                pa[u] = A[(size_t)(rowB + rr[u]) * 256 + k1 + cc[u]];
                pw[u] = W[(size_t)(k1 + rr[u]) * 256 + colB + cc[u]];
            }
        }
        #pragma unroll
        for (int kk = 0; kk < 32; ++kk) {
            float wv = Ws[kk * 33 + lane];
            #pragma unroll
            for (int r = 0; r < 4; ++r)
                acc[r] = fmaf(As[(ty * 4 + r) * 33 + kk], wv, acc[r]);
        }
        __syncthreads();
    }
    const int col = colB + lane;
    const float bv = bias ? bias[col] : 0.f;
    #pragma unroll
    for (int r = 0; r < 4; ++r)
        C[(size_t)(rowB + ty * 4 + r) * 256 + col] = acc[r] + bv;
}

// ---------------- multi-head attention core ---------------------------------
__global__ void attn_kernel(const float* __restrict__ q, int q_bs,
                            const float* __restrict__ k, const float* __restrict__ v,
                            int Lk, float* __restrict__ o)
{
    __shared__ float qs[16 * 32];
    __shared__ float sc[16 * 256];
    const int tid  = threadIdx.x;
    const int head = blockIdx.x;
    const int b    = blockIdx.y;

    const float* qb = q + (size_t)b * q_bs;
    for (int u = tid; u < 512; u += 256) {
        int l = u >> 5, d = u & 31;
        qs[u] = qb[(size_t)l * 256 + head * 32 + d];
    }
    __syncthreads();

    {
        int l = tid & 15, jg = tid >> 4;
        const float* kb = k + ((size_t)b * Lk) * 256 + head * 32;
        for (int j = jg; j < Lk; j += 16) {
            const float* kr = kb + (size_t)j * 256;
            float s = 0.f;
            #pragma unroll
            for (int d = 0; d < 32; ++d) s = fmaf(qs[l * 32 + d], kr[d], s);
            sc[l * 256 + j] = s * 0.0625f;
        }
    }
    __syncthreads();

    if (tid < 16) {
        float m = -1e30f;
        for (int j = 0; j < Lk; ++j) m = fmaxf(m, sc[tid * 256 + j]);
        float sum = 0.f;
        for (int j = 0; j < Lk; ++j) {
            float e = __expf(sc[tid * 256 + j] - m);
            sc[tid * 256 + j] = e;
            sum += e;
        }
        float inv = 1.f / sum;
        for (int j = 0; j < Lk; ++j) sc[tid * 256 + j] *= inv;
    }
    __syncthreads();

    {
        const float* vb = v + ((size_t)b * Lk) * 256 + head * 32;
        for (int u = tid; u < 512; u += 256) {
            int l = u >> 5, d = u & 31;
            float accv = qs[l * 32 + d];
            for (int j = 0; j < Lk; ++j)
                accv = fmaf(sc[l * 256 + j], vb[(size_t)j * 256 + d], accv);
            o[((size_t)(b * 16 + l)) * 256 + head * 32 + d] = accv;
        }
    }
}

// ---------------- host orchestration ---------------------------------------
static inline void launch_gemm(const float* A, const float* W, const float* bias,
                               const float* res, float* C, int M, int K, int N, int act)
{
    dim3 grid((N + 31) / 32, (M + 31) / 32);
    gemm_kernel<<<grid, 256>>>(A, W, bias, res, C, M, K, N, act);
}

extern "C" void kernel_launch(void* const* d_in, const int* in_sizes, int n_in,
                              void* d_out, int out_size)
{
    (void)in_sizes; (void)n_in; (void)out_size;
    const float* x    = (const float*)d_in[0];
    const float* adj  = (const float*)d_in[1];
    const float* ginW = (const float*)d_in[2];
    const float* ginb = (const float*)d_in[3];
    const float* geW1 = (const float*)d_in[4];
    const float* geb1 = (const float*)d_in[5];
    const float* geW2 = (const float*)d_in[6];
    const float* geb2 = (const float*)d_in[7];
    const float* gnW1 = (const float*)d_in[8];
    const float* gnb1 = (const float*)d_in[9];
    const float* gnW2 = (const float*)d_in[10];
    const float* gnb2 = (const float*)d_in[11];
    const float* goW  = (const float*)d_in[12];
    const float* gob  = (const float*)d_in[13];
    const float* S    = (const float*)d_in[14];
    const float* mWq  = (const float*)d_in[15];
    const float* mbq  = (const float*)d_in[16];
    const float* mWk  = (const float*)d_in[17];
    const float* mbk  = (const float*)d_in[18];
    const float* mWv  = (const float*)d_in[19];
    const float* mbv  = (const float*)d_in[20];
    const float* mWo  = (const float*)d_in[21];
    const float* mbo  = (const float*)d_in[22];
    const float* finW = (const float*)d_in[23];
    const float* finb = (const float*)d_in[24];
    float* out = (float*)d_out;

    float *h, *hi, *hj, *agg, *n1, *n2, *enc, *kb, *vb, *q, *oA, *m1, *m2;
    uint32_t* w2bt;
    cudaGetSymbolAddress((void**)&h,   g_h);
    cudaGetSymbolAddress((void**)&hi,  g_hi);
    cudaGetSymbolAddress((void**)&hj,  g_hj);
    cudaGetSymbolAddress((void**)&agg, g_agg);
    cudaGetSymbolAddress((void**)&n1,  g_n1);
    cudaGetSymbolAddress((void**)&n2,  g_n2);
    cudaGetSymbolAddress((void**)&enc, g_enc);
    cudaGetSymbolAddress((void**)&kb,  g_k);
    cudaGetSymbolAddress((void**)&vb,  g_v);
    cudaGetSymbolAddress((void**)&q,   g_q);
    cudaGetSymbolAddress((void**)&oA,  g_oA);
    cudaGetSymbolAddress((void**)&m1,  g_m1);
    cudaGetSymbolAddress((void**)&m2,  g_m2);
    cudaGetSymbolAddress((void**)&w2bt, g_w2bt);

    cudaFuncSetAttribute(edge_bf16_v4, cudaFuncAttributeMaxDynamicSharedMemorySize, EDGE3_SMEM);

    // 0. prep: transpose+pack W2 to bf16
    prep_w2bt<<<256, 128>>>(geW2, w2bt);
    // 1. h = x @ gin_W + gin_b
    launch_gemm(x, ginW, ginb, nullptr, h, 1024, 48, 256, 0);
    // 2+3. hi = h @ Wi ; hj = h @ Wj + geb1 (one fused launch)
    gemm_qkv<<<dim3(16, 32), 256>>>(h, geW1, geW1 + 65536, nullptr,
                                    nullptr, geb1, nullptr, hi, hj, nullptr);
    // 4. fused edge MLP + adjacency contraction -> agg
    edge_bf16_v4<<<dim3(256, 4), 512, EDGE3_SMEM>>>(hi, hj, w2bt, geb2, adj, agg);
    // 5-7. node MLP + encoder
    launch_gemm(agg, gnW1, gnb1, nullptr, n1, 1024, 256, 256, 1);
    launch_gemm(n1,  gnW2, gnb2, nullptr, n2, 1024, 256, 256, 1);
    launch_gemm(n2,  goW,  gob,  nullptr, enc, 1024, 256, 256, 0);

    // ---- MAB 0: Q = broadcast(S), K = enc (Lk=256) ----
    launch_gemm(S, mWq, mbq, nullptr, q, 16, 256, 256, 0);
    gemm_qkv<<<dim3(16, 32), 256>>>(enc, mWk, mWv, nullptr,
                                    mbk, mbv, nullptr, kb, vb, nullptr);
    attn_kernel<<<dim3(8, 4), 256>>>(q, 0, kb, vb, 256, oA);
    launch_gemm(oA, mWo, mbo, oA, m1, 64, 256, 256, 1);

    // ---- MAB 1 ----
    gemm_qkv<<<dim3(24, 2), 256>>>(m1, mWq + 65536, mWk + 65536, mWv + 65536,
                                   mbq + 256, mbk + 256, mbv + 256, q, kb, vb);
    attn_kernel<<<dim3(8, 4), 256>>>(q, 16 * 256, kb, vb, 16, oA);
    launch_gemm(oA, mWo + 65536, mbo + 256, oA, m2, 64, 256, 256, 1);

    // ---- MAB 2 ----
    gemm_qkv<<<dim3(24, 2), 256>>>(m2, mWq + 2 * 65536, mWk + 2 * 65536, mWv + 2 * 65536,
                                   mbq + 2 * 256, mbk + 2 * 256, mbv + 2 * 256, q, kb, vb);
    attn_kernel<<<dim3(8, 4), 256>>>(q, 16 * 256, kb, vb, 16, oA);
    launch_gemm(oA, mWo + 2 * 65536, mbo + 2 * 256, oA, m1, 64, 256, 256, 1);

    // ---- final: out = m1 @ finW + finb -> (B,16,384) == (B,16,12,32) ----
    launch_gemm(m1, finW, finb, nullptr, out, 64, 256, 384, 0);
}

// round 10
// speedup vs baseline: 1.8406x; 1.0417x over previous
#include <cuda_runtime.h>
#include <cuda_bf16.h>
#include <cstdint>
#include <math.h>
#include <stddef.h>

// ---------------- scratch (device globals; no allocations allowed) ----------
__device__ float g_h  [1024 * 256];
__device__ float g_hi [1024 * 256];
__device__ float g_hj [1024 * 256];
__device__ float g_agg[1024 * 256];
__device__ float g_n1 [1024 * 256];
__device__ float g_n2 [1024 * 256];
__device__ float g_enc[1024 * 256];
__device__ float g_k  [1024 * 256];
__device__ float g_v  [1024 * 256];
__device__ float g_q  [64 * 256];
__device__ float g_oA [64 * 256];
__device__ float g_m1 [64 * 256];
__device__ float g_m2 [64 * 256];
__device__ uint32_t g_w2bt[256 * 128];  // W2 transposed+packed: w2bt[n][k/2] = bf16x2(W2[k][n], W2[k+1][n])

// ---------------- helpers ----------------------------------------------------
__device__ __forceinline__ uint32_t pack_bf16x2(float lo, float hi) {
    __nv_bfloat162 p = __floats2bfloat162_rn(lo, hi);
    return *(uint32_t*)&p;
}
// m16n8k16 bf16 MMA (baseline PTX, sm_80+): D = A@B + D, row.col
__device__ __forceinline__ void mma_bf16(float* c, const uint32_t* a, const uint32_t* bf) {
    asm volatile(
        "mma.sync.aligned.m16n8k16.row.col.f32.bf16.bf16.f32 "
        "{%0,%1,%2,%3}, {%4,%5,%6,%7}, {%8,%9}, {%0,%1,%2,%3};"
        : "+f"(c[0]), "+f"(c[1]), "+f"(c[2]), "+f"(c[3])
        : "r"(a[0]), "r"(a[1]), "r"(a[2]), "r"(a[3]), "r"(bf[0]), "r"(bf[1]));
}
__device__ __forceinline__ void ldsm_x4(uint32_t* r, uint32_t saddr) {
    asm volatile("ldmatrix.sync.aligned.m8n8.x4.shared.b16 {%0,%1,%2,%3}, [%4];"
        : "=r"(r[0]), "=r"(r[1]), "=r"(r[2]), "=r"(r[3]) : "r"(saddr));
}

// ---------------- prep: W2 (256x256 row-major [k][n]) -> packed bf16 [n][k/2]
__global__ void prep_w2bt(const float* __restrict__ W2, uint32_t* __restrict__ w2bt) {
    int n = blockIdx.x, c = threadIdx.x;
    w2bt[n * 128 + c] = pack_bf16x2(W2[(2 * c) * 256 + n], W2[(2 * c + 1) * 256 + n]);
}

// ---------------- edge v6: resident W, 4 steps (jh x kc), interleaved fill ---
// Per block (i, b): W[256n x 256k] resident in SMEM (filled once).
// Steps s = (jh<<1)|kc: A[128j x 128k] = bf16(relu(hi + hj_chunk))  (buf s&1)
//   C += A @ Wslice(kc); after kc=1 of each jh: fold adj-weighted relu(C+b2).
// Step s+1's A-fill interleaved one pass per ks inside step s's MMA loop.
// 512 threads = 16 warps: jm = w&1 (64j), hn = w>>1 (32h each, 256h total).
static constexpr int APW = 68;            // A row pitch (u32): 64 data (128 bf16) + 4 pad
static constexpr int WPW = 132;           // W row pitch (u32): 128 data (256 bf16) + 4 pad
static constexpr int EV_A  = 128 * APW;   // 8704 u32 per A buf
static constexpr int EV_W  = 256 * WPW;   // 33792 u32
static constexpr int EV_U32 = 2 * EV_A + EV_W;            // 51200
static constexpr int EDGE6_SMEM = (EV_U32 + 1280) * 4;    // 209920 B

__global__ void __launch_bounds__(512, 1)
edge_bf16_v6(const float* __restrict__ hi, const float* __restrict__ hjp,
             const uint32_t* __restrict__ w2bt, const float* __restrict__ b2,
             const float* __restrict__ adj, float* __restrict__ agg)
{
    extern __shared__ uint32_t smu[];
    uint32_t* Abufs = smu;                     // [2][128*APW]
    uint32_t* Wbuf  = smu + 2 * EV_A;          // [256*WPW]
    float* ci   = (float*)(smu + EV_U32);
    float* adjs = ci + 256;
    float* b2s  = adjs + 256;
    float* part = b2s + 256;                   // 512 floats

    const int tid = threadIdx.x, lane = tid & 31, w = tid >> 5;
    const int i = blockIdx.x, b = blockIdx.y;
    const size_t row = (size_t)(b * 256 + i) * 256;

    if (tid < 256) {
        ci[tid]   = hi[row + tid];
        adjs[tid] = adj[row + tid];
        b2s[tid]  = b2[tid];
    }
    __syncthreads();   // ci visible to fills below

    const int g  = lane >> 2;      // 0..7
    const int tg = lane & 3;       // 0..3
    const int jm = w & 1;          // j half (64)
    const int hn = w >> 1;         // h tile 0..7 (32 wide)

    const float* hjb = hjp + (size_t)b * 65536;
    const int kq = lane;           // float4 column within 128-k chunk (0..31)
    const int jr = w;              // row base per fill pass (0..15)

    // per-thread ci slices for the two 128-k chunks
    const float4 cv0 = *(const float4*)(ci + kq * 4);
    const float4 cv1 = *(const float4*)(ci + 128 + kq * 4);

    // ldmatrix byte offsets
    const uint32_t smemS = (uint32_t)__cvta_generic_to_shared(smu);
    const uint32_t aTh = (uint32_t)((lane & 15) * (APW * 4) + (lane >> 4) * 16);
    const uint32_t wTh = (uint32_t)((((lane >> 4) & 1) * 8 + (lane & 7)) * (WPW * 4)
                                    + ((lane >> 3) & 1) * 16);
    const uint32_t Wbase = smemS + 2 * EV_A * 4 + hn * 32 * (WPW * 4) + wTh;

    float C[4][4][4];
    #pragma unroll
    for (int mt = 0; mt < 4; ++mt)
        #pragma unroll
        for (int nt = 0; nt < 4; ++nt)
            #pragma unroll
            for (int r = 0; r < 4; ++r) C[mt][nt][r] = 0.f;
    float ps[4][2];
    #pragma unroll
    for (int nt = 0; nt < 4; ++nt) { ps[nt][0] = 0.f; ps[nt][1] = 0.f; }

    // one fill pass (16 rows) of step s's A chunk into buf s&1
    auto fillA_pass = [&](int s, int p) {
        const int jh = s >> 1, kc = s & 1;
        const int r = p * 16 + jr;
        const float4 cv = kc ? cv1 : cv0;
        float4 hv = *(const float4*)(hjb + (size_t)(jh * 128 + r) * 256 + kc * 128 + kq * 4);
        uint2 o;
        o.x = pack_bf16x2(fmaxf(cv.x + hv.x, 0.f), fmaxf(cv.y + hv.y, 0.f));
        o.y = pack_bf16x2(fmaxf(cv.z + hv.z, 0.f), fmaxf(cv.w + hv.w, 0.f));
        *(uint2*)(Abufs + (s & 1) * EV_A + r * APW + kq * 2) = o;
    };

    // prolog: resident W (256 rows x 128 u32) + step-0 A chunk
    {
        #pragma unroll
        for (int p = 0; p < 16; ++p) {
            const int r = p * 16 + jr;
            uint4 wv = *(const uint4*)(w2bt + (size_t)r * 128 + kq * 4);
            *(uint4*)(Wbuf + r * WPW + kq * 4) = wv;
        }
        #pragma unroll
        for (int p = 0; p < 8; ++p) fillA_pass(0, p);
    }
    __syncthreads();

    for (int s = 0; s < 4; ++s) {
        const int kc = s & 1, jh = s >> 1;
        const uint32_t Abase = smemS + (uint32_t)((s & 1) * EV_A * 4)
                             + jm * 64 * (APW * 4) + aTh;
        const uint32_t Wk = Wbase + (uint32_t)(kc * 256);   // kc*128 bf16 = 256 B
        #pragma unroll
        for (int ks = 0; ks < 8; ++ks) {
            uint32_t afr[4][4], bfr[4][2];
            #pragma unroll
            for (int mt = 0; mt < 4; ++mt)
                ldsm_x4(afr[mt], Abase + mt * 16 * (APW * 4) + ks * 32);
            #pragma unroll
            for (int p = 0; p < 2; ++p) {
                uint32_t tmp[4];
                ldsm_x4(tmp, Wk + p * 16 * (WPW * 4) + ks * 32);
                bfr[2 * p][0] = tmp[0]; bfr[2 * p][1] = tmp[1];
                bfr[2 * p + 1][0] = tmp[2]; bfr[2 * p + 1][1] = tmp[3];
            }
            #pragma unroll
            for (int mt = 0; mt < 4; ++mt)
                #pragma unroll
                for (int nt = 0; nt < 4; ++nt)
                    mma_bf16(C[mt][nt], afr[mt], bfr[nt]);
            // interleave next step's A-fill (writes the other buffer)
            if (s < 3) fillA_pass(s + 1, ks);
        }
        // end of a jh (kc==1): fold C into adj-weighted per-lane partials
        if (kc == 1) {
            #pragma unroll
            for (int mt = 0; mt < 4; ++mt) {
                const float aj0 = adjs[jh * 128 + jm * 64 + mt * 16 + g];
                const float aj8 = adjs[jh * 128 + jm * 64 + mt * 16 + g + 8];
                #pragma unroll
                for (int nt = 0; nt < 4; ++nt) {
                    #pragma unroll
                    for (int c = 0; c < 2; ++c) {
                        const float bv = b2s[hn * 32 + nt * 8 + 2 * tg + c];
                        ps[nt][c] += aj0 * fmaxf(C[mt][nt][c]     + bv, 0.f)
                                   + aj8 * fmaxf(C[mt][nt][2 + c] + bv, 0.f);
                        C[mt][nt][c] = 0.f;
                        C[mt][nt][2 + c] = 0.f;
                    }
                }
            }
        }
        __syncthreads();   // next step reads the buffer just filled
    }

    // ---- final reduce over g (lane = 4g+tg), combine jm halves, store ------
    #pragma unroll
    for (int off = 16; off >= 4; off >>= 1)
        #pragma unroll
        for (int nt = 0; nt < 4; ++nt)
            #pragma unroll
            for (int c = 0; c < 2; ++c)
                ps[nt][c] += __shfl_down_sync(0xffffffffu, ps[nt][c], off);
    if (lane < 4) {
        #pragma unroll
        for (int nt = 0; nt < 4; ++nt)
            #pragma unroll
            for (int c = 0; c < 2; ++c)
                part[w * 32 + nt * 8 + 2 * lane + c] = ps[nt][c];
    }
    __syncthreads();
    if (tid < 256) {
        const int hq = tid >> 5, hl = tid & 31;
        agg[row + tid] = part[(2 * hq) * 32 + hl] + part[(2 * hq + 1) * 32 + hl];
    }
}

// ---------------- fp32 tiled GEMM, register double-buffered -----------------
__global__ void gemm_kernel(const float* __restrict__ A, const float* __restrict__ W,
                            const float* __restrict__ bias, const float* __restrict__ res,
                            float* __restrict__ C, int M, int K, int N, int act)
{
    __shared__ float As[32 * 33];
    __shared__ float Ws[32 * 33];
    const int tid  = threadIdx.x;
    const int lane = tid & 31;
    const int ty   = tid >> 5;
    const int colB = blockIdx.x * 32;
    const int rowB = blockIdx.y * 32;

    float acc[4] = {0.f, 0.f, 0.f, 0.f};
    float pa[4], pw[4];
    int rr[4], cc[4];
    #pragma unroll
    for (int u = 0; u < 4; ++u) { int idx = tid + u * 256; rr[u] = idx >> 5; cc[u] = idx & 31; }

    #pragma unroll
    for (int u = 0; u < 4; ++u) {
        int gr = rowB + rr[u], gk = cc[u];
        pa[u] = (gr < M && gk < K) ? A[(size_t)gr * K + gk] : 0.f;
        int wk = rr[u], wc = colB + cc[u];
        pw[u] = (wk < K && wc < N) ? W[(size_t)wk * N + wc] : 0.f;
    }

    for (int k0 = 0; k0 < K; k0 += 32) {
        #pragma unroll
        for (int u = 0; u < 4; ++u) {
            As[rr[u] * 33 + cc[u]] = pa[u];
            Ws[rr[u] * 33 + cc[u]] = pw[u];
        }
        __syncthreads();
        const int k1 = k0 + 32;
        if (k1 < K) {
            #pragma unroll
            for (int u = 0; u < 4; ++u) {
                int gr = rowB + rr[u], gk = k1 + cc[u];
                pa[u] = (gr < M && gk < K) ? A[(size_t)gr * K + gk] : 0.f;
                int wk = k1 + rr[u], wc = colB + cc[u];
                pw[u] = (wk < K && wc < N) ? W[(size_t)wk * N + wc] : 0.f;
            }
        }
        #pragma unroll
        for (int kk = 0; kk < 32; ++kk) {
            float wv = Ws[kk * 33 + lane];
            #pragma unroll
            for (int r = 0; r < 4; ++r)
                acc[r] = fmaf(As[(ty * 4 + r) * 33 + kk], wv, acc[r]);
        }
        __syncthreads();
    }

    int col = colB + lane;
    if (col < N) {
        float bv = bias ? bias[col] : 0.f;
        #pragma unroll
        for (int r = 0; r < 4; ++r) {
            int rowi = rowB + ty * 4 + r;
            if (rowi < M) {
                float v = acc[r] + bv;
                if (act) v = fmaxf(v, 0.f);
                if (res) v += res[(size_t)rowi * N + col];
                C[(size_t)rowi * N + col] = v;
            }
        }
    }
}

// ---------------- fused multi-weight GEMM (K=N=256, M % 32 == 0) ------------
__global__ void gemm_qkv(const float* __restrict__ A,
                         const float* __restrict__ W0, const float* __restrict__ W1,
                         const float* __restrict__ W2,
                         const float* __restrict__ b0, const float* __restrict__ b1,
                         const float* __restrict__ b2,
                         float* __restrict__ C0, float* __restrict__ C1,
                         float* __restrict__ C2)
{
    __shared__ float As[32 * 33];
    __shared__ float Ws[32 * 33];
    const int tid = threadIdx.x, lane = tid & 31, ty = tid >> 5;
    const int sel  = blockIdx.x >> 3;
    const int colB = (blockIdx.x & 7) * 32;
    const int rowB = blockIdx.y * 32;
    const float* W    = sel == 0 ? W0 : (sel == 1 ? W1 : W2);
    const float* bias = sel == 0 ? b0 : (sel == 1 ? b1 : b2);
    float*       C    = sel == 0 ? C0 : (sel == 1 ? C1 : C2);

    float acc[4] = {0.f, 0.f, 0.f, 0.f};
    float pa[4], pw[4];
    int rr[4], cc[4];
    #pragma unroll
    for (int u = 0; u < 4; ++u) { int idx = tid + u * 256; rr[u] = idx >> 5; cc[u] = idx & 31; }
    #pragma unroll
    for (int u = 0; u < 4; ++u) {
        pa[u] = A[(size_t)(rowB + rr[u]) * 256 + cc[u]];
        pw[u] = W[(size_t)rr[u] * 256 + colB + cc[u]];
    }

    for (int k0 = 0; k0 < 256; k0 += 32) {
        #pragma unroll
        for (int u = 0; u < 4; ++u) {
            As[rr[u] * 33 + cc[u]] = pa[u];
            Ws[rr[u] * 33 + cc[u]] = pw[u];
        }
        __syncthreads();
        const int k1 = k0 + 32;
        if (k1 < 256) {
            #pragma unroll
            for (int u = 0; u < 4; ++u) {
                pa[u] = A[(size_t)(rowB + rr[u]) * 256 + k1 + cc[u]];
                pw[u] = W[(size_t)(k1 + rr[u]) * 256 + colB + cc[u]];
            }
        }
        #pragma unroll
        for (int kk = 0; kk < 32; ++kk) {
            float wv = Ws[kk * 33 + lane];
            #pragma unroll
            for (int r = 0; r < 4; ++r)
                acc[r] = fmaf(As[(ty * 4 + r) * 33 + kk], wv, acc[r]);
        }
        __syncthreads();
    }
    const int col = colB + lane;
    const float bv = bias ? bias[col] : 0.f;
    #pragma unroll
    for (int r = 0; r < 4; ++r)
        C[(size_t)(rowB + ty * 4 + r) * 256 + col] = acc[r] + bv;
}

// ---------------- multi-head attention core ---------------------------------
__global__ void attn_kernel(const float* __restrict__ q, int q_bs,
                            const float* __restrict__ k, const float* __restrict__ v,
                            int Lk, float* __restrict__ o)
{
    __shared__ float qs[16 * 32];
    __shared__ float sc[16 * 256];
    const int tid  = threadIdx.x;
    const int head = blockIdx.x;
    const int b    = blockIdx.y;

    const float* qb = q + (size_t)b * q_bs;
    for (int u = tid; u < 512; u += 256) {
        int l = u >> 5, d = u & 31;
        qs[u] = qb[(size_t)l * 256 + head * 32 + d];
    }
    __syncthreads();

    {
        int l = tid & 15, jg = tid >> 4;
        const float* kb = k + ((size_t)b * Lk) * 256 + head * 32;
        for (int j = jg; j < Lk; j += 16) {
            const float* kr = kb + (size_t)j * 256;
            float s = 0.f;
            #pragma unroll
            for (int d = 0; d < 32; ++d) s = fmaf(qs[l * 32 + d], kr[d], s);
            sc[l * 256 + j] = s * 0.0625f;
        }
    }
    __syncthreads();

    if (tid < 16) {
        float m = -1e30f;
        for (int j = 0; j < Lk; ++j) m = fmaxf(m, sc[tid * 256 + j]);
        float sum = 0.f;
        for (int j = 0; j < Lk; ++j) {
            float e = __expf(sc[tid * 256 + j] - m);
            sc[tid * 256 + j] = e;
            sum += e;
        }
        float inv = 1.f / sum;
        for (int j = 0; j < Lk; ++j) sc[tid * 256 + j] *= inv;
    }
    __syncthreads();

    {
        const float* vb = v + ((size_t)b * Lk) * 256 + head * 32;
        for (int u = tid; u < 512; u += 256) {
            int l = u >> 5, d = u & 31;
            float accv = qs[l * 32 + d];
            for (int j = 0; j < Lk; ++j)
                accv = fmaf(sc[l * 256 + j], vb[(size_t)j * 256 + d], accv);
            o[((size_t)(b * 16 + l)) * 256 + head * 32 + d] = accv;
        }
    }
}

// ---------------- host orchestration ---------------------------------------
static inline void launch_gemm(const float* A, const float* W, const float* bias,
                               const float* res, float* C, int M, int K, int N, int act)
{
    dim3 grid((N + 31) / 32, (M + 31) / 32);
    gemm_kernel<<<grid, 256>>>(A, W, bias, res, C, M, K, N, act);
}

extern "C" void kernel_launch(void* const* d_in, const int* in_sizes, int n_in,
                              void* d_out, int out_size)
{
    (void)in_sizes; (void)n_in; (void)out_size;
    const float* x    = (const float*)d_in[0];
    const float* adj  = (const float*)d_in[1];
    const float* ginW = (const float*)d_in[2];
    const float* ginb = (const float*)d_in[3];
    const float* geW1 = (const float*)d_in[4];
    const float* geb1 = (const float*)d_in[5];
    const float* geW2 = (const float*)d_in[6];
    const float* geb2 = (const float*)d_in[7];
    const float* gnW1 = (const float*)d_in[8];
    const float* gnb1 = (const float*)d_in[9];
    const float* gnW2 = (const float*)d_in[10];
    const float* gnb2 = (const float*)d_in[11];
    const float* goW  = (const float*)d_in[12];
    const float* gob  = (const float*)d_in[13];
    const float* S    = (const float*)d_in[14];
    const float* mWq  = (const float*)d_in[15];
    const float* mbq  = (const float*)d_in[16];
    const float* mWk  = (const float*)d_in[17];
    const float* mbk  = (const float*)d_in[18];
    const float* mWv  = (const float*)d_in[19];
    const float* mbv  = (const float*)d_in[20];
    const float* mWo  = (const float*)d_in[21];
    const float* mbo  = (const float*)d_in[22];
    const float* finW = (const float*)d_in[23];
    const float* finb = (const float*)d_in[24];
    float* out = (float*)d_out;

    float *h, *hi, *hj, *agg, *n1, *n2, *enc, *kb, *vb, *q, *oA, *m1, *m2;
    uint32_t* w2bt;
    cudaGetSymbolAddress((void**)&h,   g_h);
    cudaGetSymbolAddress((void**)&hi,  g_hi);
    cudaGetSymbolAddress((void**)&hj,  g_hj);
    cudaGetSymbolAddress((void**)&agg, g_agg);
    cudaGetSymbolAddress((void**)&n1,  g_n1);
    cudaGetSymbolAddress((void**)&n2,  g_n2);
    cudaGetSymbolAddress((void**)&enc, g_enc);
    cudaGetSymbolAddress((void**)&kb,  g_k);
    cudaGetSymbolAddress((void**)&vb,  g_v);
    cudaGetSymbolAddress((void**)&q,   g_q);
    cudaGetSymbolAddress((void**)&oA,  g_oA);
    cudaGetSymbolAddress((void**)&m1,  g_m1);
    cudaGetSymbolAddress((void**)&m2,  g_m2);
    cudaGetSymbolAddress((void**)&w2bt, g_w2bt);

    cudaFuncSetAttribute(edge_bf16_v6, cudaFuncAttributeMaxDynamicSharedMemorySize, EDGE6_SMEM);

    // 0. prep: transpose+pack W2 to bf16
    prep_w2bt<<<256, 128>>>(geW2, w2bt);
    // 1. h = x @ gin_W + gin_b
    launch_gemm(x, ginW, ginb, nullptr, h, 1024, 48, 256, 0);
    // 2+3. hi = h @ Wi ; hj = h @ Wj + geb1 (one fused launch)
    gemm_qkv<<<dim3(16, 32), 256>>>(h, geW1, geW1 + 65536, nullptr,
                                    nullptr, geb1, nullptr, hi, hj, nullptr);
    // 4. fused edge MLP + adjacency contraction -> agg
    edge_bf16_v6<<<dim3(256, 4), 512, EDGE6_SMEM>>>(hi, hj, w2bt, geb2, adj, agg);
    // 5-7. node MLP + encoder
    launch_gemm(agg, gnW1, gnb1, nullptr, n1, 1024, 256, 256, 1);
    launch_gemm(n1,  gnW2, gnb2, nullptr, n2, 1024, 256, 256, 1);
    launch_gemm(n2,  goW,  gob,  nullptr, enc, 1024, 256, 256, 0);

    // ---- MAB 0: Q = broadcast(S), K = enc (Lk=256) ----
    launch_gemm(S, mWq, mbq, nullptr, q, 16, 256, 256, 0);
    gemm_qkv<<<dim3(16, 32), 256>>>(enc, mWk, mWv, nullptr,
                                    mbk, mbv, nullptr, kb, vb, nullptr);
    attn_kernel<<<dim3(8, 4), 256>>>(q, 0, kb, vb, 256, oA);
    launch_gemm(oA, mWo, mbo, oA, m1, 64, 256, 256, 1);

    // ---- MAB 1 ----
    gemm_qkv<<<dim3(24, 2), 256>>>(m1, mWq + 65536, mWk + 65536, mWv + 65536,
                                   mbq + 256, mbk + 256, mbv + 256, q, kb, vb);
    attn_kernel<<<dim3(8, 4), 256>>>(q, 16 * 256, kb, vb, 16, oA);
    launch_gemm(oA, mWo + 65536, mbo + 256, oA, m2, 64, 256, 256, 1);

    // ---- MAB 2 ----
    gemm_qkv<<<dim3(24, 2), 256>>>(m2, mWq + 2 * 65536, mWk + 2 * 65536, mWv + 2 * 65536,
                                   mbq + 2 * 256, mbk + 2 * 256, mbv + 2 * 256, q, kb, vb);
    attn_kernel<<<dim3(8, 4), 256>>>(q, 16 * 256, kb, vb, 16, oA);
    launch_gemm(oA, mWo + 2 * 65536, mbo + 2 * 256, oA, m1, 64, 256, 256, 1);

    // ---- final: out = m1 @ finW + finb -> (B,16,384) == (B,16,12,32) ----
    launch_gemm(m1, finW, finb, nullptr, out, 64, 256, 384, 0);
}